// round 1
// baseline (speedup 1.0000x reference)
#include <cuda_runtime.h>
#include <cuda_bf16.h>
#include <cstdint>

// ---------------------------------------------------------------------------
// Problem: fused transformer block, fp32.
//   x[4,1024,1024], Wqkv[3072,1024], bqkv[3072], W1[1024,1024], b1[1024]
//   qkv = x @ Wqkv^T + bqkv            (M=4096, N=3072, K=1024)
//   attention: 16 heads, d=64, scale = 1024^-0.5
//   out = attn_out @ W1^T + b1         (M=4096, N=1024, K=1024)
// ---------------------------------------------------------------------------

#define BATCH   4
#define SEQ     1024
#define DIM     1024
#define HEADS   16
#define HDIM    64
#define ROWS    (BATCH * SEQ)      // 4096
#define QKVDIM  (3 * DIM)          // 3072

// Scratch (device globals; no allocation allowed in kernel_launch)
__device__ float g_qkv[ROWS * QKVDIM];     // [row][3][h][d]
__device__ float g_attn[ROWS * DIM];       // [row][h*64+d]

// ---------------------------------------------------------------------------
// Tiled NT GEMM with bias:  C[M,N] = A[M,K] @ B[N,K]^T + bias[N]
// Block tile 64x64, K-step 16, 256 threads, 4x4 per-thread micro-tile.
// ---------------------------------------------------------------------------
__global__ __launch_bounds__(256) void gemm_nt_bias(
    const float* __restrict__ A, const float* __restrict__ B,
    const float* __restrict__ bias, float* __restrict__ C,
    int M, int N, int K)
{
    __shared__ float As[16][68];   // [kk][m], padded
    __shared__ float Bs[16][68];   // [kk][n], padded

    const int tid = threadIdx.x;
    const int tx  = tid & 15;      // n direction
    const int ty  = tid >> 4;      // m direction
    const int m0  = blockIdx.y * 64;
    const int n0  = blockIdx.x * 64;

    float acc[4][4];
#pragma unroll
    for (int i = 0; i < 4; i++)
#pragma unroll
        for (int j = 0; j < 4; j++) acc[i][j] = 0.0f;

    const int kk     = tid & 15;
    const int m_base = tid >> 4;

    for (int k0 = 0; k0 < K; k0 += 16) {
#pragma unroll
        for (int p = 0; p < 4; p++) {
            const int mm = m_base + p * 16;
            As[kk][mm] = A[(size_t)(m0 + mm) * K + k0 + kk];
            Bs[kk][mm] = B[(size_t)(n0 + mm) * K + k0 + kk];
        }
        __syncthreads();

#pragma unroll
        for (int k = 0; k < 16; k++) {
            float av[4], bv[4];
            *(float4*)av = *(const float4*)&As[k][ty * 4];
            *(float4*)bv = *(const float4*)&Bs[k][tx * 4];
#pragma unroll
            for (int i = 0; i < 4; i++)
#pragma unroll
                for (int j = 0; j < 4; j++)
                    acc[i][j] += av[i] * bv[j];
        }
        __syncthreads();
    }

#pragma unroll
    for (int i = 0; i < 4; i++) {
        const int m = m0 + ty * 4 + i;
#pragma unroll
        for (int j = 0; j < 4; j++) {
            const int n = n0 + tx * 4 + j;
            C[(size_t)m * N + n] = acc[i][j] + bias[n];
        }
    }
}

// ---------------------------------------------------------------------------
// Flash attention, fp32, online softmax.
// Grid: (SEQ/64, HEADS, BATCH). Block: 256 threads.
// Each block: 64 query rows of one (b,h); loops over 16 K/V tiles of 64.
// Dynamic smem layout (floats):
//   Qs[64][65]  Ks[64][65]  Vs[64][68]  St[64][68](col-major S)  m/l/alpha[64]
// ---------------------------------------------------------------------------
#define QS_LD 65
#define VS_LD 68
#define SM_QS 0
#define SM_KS (SM_QS + 64 * QS_LD)
#define SM_VS (SM_KS + 64 * QS_LD)
#define SM_ST (SM_VS + 64 * VS_LD)
#define SM_M  (SM_ST + 64 * VS_LD)
#define SM_L  (SM_M + 64)
#define SM_AL (SM_L + 64)
#define SM_TOTAL (SM_AL + 64)

__global__ __launch_bounds__(256) void flash_attn(
    const float* __restrict__ qkv, float* __restrict__ out)
{
    extern __shared__ float sm[];
    float* Qs = sm + SM_QS;
    float* Ks = sm + SM_KS;
    float* Vs = sm + SM_VS;
    float* St = sm + SM_ST;
    float* m_s = sm + SM_M;
    float* l_s = sm + SM_L;
    float* al_s = sm + SM_AL;

    const int tid = threadIdx.x;
    const int tx  = tid & 15;      // d direction (output cols)
    const int ty  = tid >> 4;      // row direction
    const int qt  = blockIdx.x;
    const int h   = blockIdx.y;
    const int b   = blockIdx.z;
    const int q0  = qt * 64;
    const float scale = 0.03125f;  // 1024^-0.5

    const float* qb = qkv + (size_t)b * SEQ * QKVDIM + (size_t)h * HDIM;
    const float* kb = qb + DIM;
    const float* vb = qb + 2 * DIM;

    // Load Q tile (64 rows x 64 d)
    for (int idx = tid; idx < 64 * 64; idx += 256) {
        const int d = idx & 63;
        const int r = idx >> 6;
        Qs[r * QS_LD + d] = qb[(size_t)(q0 + r) * QKVDIM + d];
    }
    if (tid < 64) { m_s[tid] = -1e30f; l_s[tid] = 0.0f; }

    float o_acc[4][4];
#pragma unroll
    for (int i = 0; i < 4; i++)
#pragma unroll
        for (int j = 0; j < 4; j++) o_acc[i][j] = 0.0f;

    for (int jt = 0; jt < SEQ / 64; jt++) {
        const int j0 = jt * 64;
        __syncthreads();   // protect Ks/Vs/St from previous iteration readers
        for (int idx = tid; idx < 64 * 64; idx += 256) {
            const int d = idx & 63;
            const int c = idx >> 6;
            Ks[c * QS_LD + d] = kb[(size_t)(j0 + c) * QKVDIM + d];
            Vs[c * VS_LD + d] = vb[(size_t)(j0 + c) * QKVDIM + d];
        }
        __syncthreads();

        // S = Q @ K^T * scale ; store transposed St[col][row]
        float s[4][4];
#pragma unroll
        for (int i = 0; i < 4; i++)
#pragma unroll
            for (int j = 0; j < 4; j++) s[i][j] = 0.0f;

        for (int d = 0; d < 64; d++) {
            float qv[4], kv[4];
#pragma unroll
            for (int i = 0; i < 4; i++) qv[i] = Qs[(ty * 4 + i) * QS_LD + d];
#pragma unroll
            for (int j = 0; j < 4; j++) kv[j] = Ks[(tx * 4 + j) * QS_LD + d];
#pragma unroll
            for (int i = 0; i < 4; i++)
#pragma unroll
                for (int j = 0; j < 4; j++)
                    s[i][j] += qv[i] * kv[j];
        }
#pragma unroll
        for (int i = 0; i < 4; i++)
#pragma unroll
            for (int j = 0; j < 4; j++)
                St[(tx * 4 + j) * VS_LD + (ty * 4 + i)] = s[i][j] * scale;
        __syncthreads();

        // Online softmax row update (one thread per row)
        if (tid < 64) {
            const int r = tid;
            const float m_old = m_s[r];
            float mx = m_old;
#pragma unroll 8
            for (int c = 0; c < 64; c++)
                mx = fmaxf(mx, St[c * VS_LD + r]);
            const float alpha = __expf(m_old - mx);
            float sum = 0.0f;
#pragma unroll 8
            for (int c = 0; c < 64; c++) {
                const float p = __expf(St[c * VS_LD + r] - mx);
                St[c * VS_LD + r] = p;
                sum += p;
            }
            l_s[r] = l_s[r] * alpha + sum;
            m_s[r] = mx;
            al_s[r] = alpha;
        }
        __syncthreads();

        // Rescale O and accumulate O += P @ V
        float a_i[4];
#pragma unroll
        for (int i = 0; i < 4; i++) a_i[i] = al_s[ty * 4 + i];
#pragma unroll
        for (int i = 0; i < 4; i++)
#pragma unroll
            for (int j = 0; j < 4; j++) o_acc[i][j] *= a_i[i];

        for (int j = 0; j < 64; j++) {
            float pv[4], vv[4];
            *(float4*)pv = *(const float4*)&St[j * VS_LD + ty * 4];
            *(float4*)vv = *(const float4*)&Vs[j * VS_LD + tx * 4];
#pragma unroll
            for (int i = 0; i < 4; i++)
#pragma unroll
                for (int k = 0; k < 4; k++)
                    o_acc[i][k] += pv[i] * vv[k];
        }
    }

    // Finalize: divide by l, write out[row][h*64+d]
    __syncthreads();
#pragma unroll
    for (int i = 0; i < 4; i++) {
        const int r = ty * 4 + i;
        const float inv_l = 1.0f / l_s[r];
        const size_t row = (size_t)b * SEQ + q0 + r;
#pragma unroll
        for (int k = 0; k < 4; k++) {
            out[row * DIM + h * HDIM + tx * 4 + k] = o_acc[i][k] * inv_l;
        }
    }
}

// ---------------------------------------------------------------------------
// Launch
// ---------------------------------------------------------------------------
extern "C" void kernel_launch(void* const* d_in, const int* in_sizes, int n_in,
                              void* d_out, int out_size)
{
    const float* x    = (const float*)d_in[0];
    const float* Wqkv = (const float*)d_in[1];
    const float* bqkv = (const float*)d_in[2];
    const float* W1   = (const float*)d_in[3];
    const float* b1   = (const float*)d_in[4];
    float* out = (float*)d_out;

    float* qkv_ptr;
    float* attn_ptr;
    cudaGetSymbolAddress((void**)&qkv_ptr, g_qkv);
    cudaGetSymbolAddress((void**)&attn_ptr, g_attn);

    // 1) QKV projection: [4096,3072] = x @ Wqkv^T + bqkv
    {
        dim3 grid(QKVDIM / 64, ROWS / 64);
        gemm_nt_bias<<<grid, 256>>>(x, Wqkv, bqkv, qkv_ptr, ROWS, QKVDIM, DIM);
    }

    // 2) Flash attention
    {
        const int smem_bytes = SM_TOTAL * (int)sizeof(float);
        cudaFuncSetAttribute(flash_attn,
                             cudaFuncAttributeMaxDynamicSharedMemorySize,
                             smem_bytes);
        dim3 grid(SEQ / 64, HEADS, BATCH);
        flash_attn<<<grid, 256, smem_bytes>>>(qkv_ptr, attn_ptr);
    }

    // 3) Output projection: [4096,1024] = attn @ W1^T + b1
    {
        dim3 grid(DIM / 64, ROWS / 64);
        gemm_nt_bias<<<grid, 256>>>(attn_ptr, W1, b1, out, ROWS, DIM, DIM);
    }
}

// round 3
// speedup vs baseline: 1.7481x; 1.7481x over previous
#include <cuda_runtime.h>
#include <cuda_bf16.h>
#include <cstdint>

// ---------------------------------------------------------------------------
// Fused transformer block, fp32 in/out.
//   qkv = x @ Wqkv^T + bqkv   (M=4096, N=3072, K=1024) -> mma.sync tf32 (HMMA)
//   attention: 16 heads, d=64, scale = 1024^-0.5       -> SIMT (R1)
//   out = attn @ W1^T + b1    (M=4096, N=1024, K=1024) -> mma.sync tf32 (HMMA)
// NOTE: tcgen05 PTX is rejected by this toolchain's compute_103 (non-'a')
// target; mma.sync is the plain-target tensor-core path.
// ---------------------------------------------------------------------------

#define BATCH   4
#define SEQ     1024
#define DIM     1024
#define HEADS   16
#define HDIM    64
#define ROWS    (BATCH * SEQ)      // 4096
#define QKVDIM  (3 * DIM)          // 3072

// Scratch (device globals; allocation is forbidden in kernel_launch)
__device__ __align__(256) float g_qkv[ROWS * QKVDIM];   // [row][3][h][d]
__device__ __align__(256) float g_attn[ROWS * DIM];     // [row][h*64+d]
__device__ __align__(256) float g_xr[ROWS * DIM];       // tf32-rounded x
__device__ __align__(256) float g_wr[QKVDIM * DIM];     // tf32-rounded Wqkv
__device__ __align__(256) float g_w1r[DIM * DIM];       // tf32-rounded W1

// ===========================================================================
// helpers
// ===========================================================================
__device__ __forceinline__ uint32_t smem_u32(const void* p) {
    uint32_t a;
    asm("{ .reg .u64 t; cvta.to.shared.u64 t, %1; cvt.u32.u64 %0, t; }"
        : "=r"(a) : "l"(p));
    return a;
}

__device__ __forceinline__ uint32_t lds32(uint32_t addr) {
    uint32_t v;
    asm volatile("ld.shared.b32 %0, [%1];" : "=r"(v) : "r"(addr));
    return v;
}

__device__ __forceinline__ void cp16(uint32_t dst, const void* src) {
    asm volatile("cp.async.cg.shared.global [%0], [%1], 16;" :: "r"(dst), "l"(src));
}
#define CP_COMMIT() asm volatile("cp.async.commit_group;" ::: "memory")
#define CP_WAIT(n)  asm volatile("cp.async.wait_group %0;" :: "n"(n) : "memory")

// m16n8k8 tf32 mma: D += A*B, row.col
__device__ __forceinline__ void mma_16n8k8(
    float* c, const uint32_t* a, const uint32_t* b)
{
    asm volatile(
        "mma.sync.aligned.m16n8k8.row.col.f32.tf32.tf32.f32 "
        "{%0,%1,%2,%3}, {%4,%5,%6,%7}, {%8,%9}, {%0,%1,%2,%3};"
        : "+f"(c[0]), "+f"(c[1]), "+f"(c[2]), "+f"(c[3])
        : "r"(a[0]), "r"(a[1]), "r"(a[2]), "r"(a[3]), "r"(b[0]), "r"(b[1]));
}

// ===========================================================================
// tf32 rounding kernel (cvt.rna.tf32.f32), float4 vectorized
// ===========================================================================
__global__ __launch_bounds__(256) void round_tf32(
    const float* __restrict__ in, float* __restrict__ out, int n4)
{
    int i = blockIdx.x * blockDim.x + threadIdx.x;
    if (i >= n4) return;
    float4 v = ((const float4*)in)[i];
    uint32_t a, b, c, d;
    asm("cvt.rna.tf32.f32 %0, %1;" : "=r"(a) : "f"(v.x));
    asm("cvt.rna.tf32.f32 %0, %1;" : "=r"(b) : "f"(v.y));
    asm("cvt.rna.tf32.f32 %0, %1;" : "=r"(c) : "f"(v.z));
    asm("cvt.rna.tf32.f32 %0, %1;" : "=r"(d) : "f"(v.w));
    float4 o;
    o.x = __uint_as_float(a); o.y = __uint_as_float(b);
    o.z = __uint_as_float(c); o.w = __uint_as_float(d);
    ((float4*)out)[i] = o;
}

// ===========================================================================
// mma.sync tf32 NT GEMM with bias:  C[M,N] = A[M,K] @ B[N,K]^T + bias[N]
// CTA tile 128x128, K-tile 32, double-buffered cp.async, 256 threads.
// Warp grid 4(m) x 2(n); warp tile 32x64; 16 HMMAs per warp per k8.
// smem rows padded to 36 floats (144B): cp.async 16B-aligned AND
// conflict-free fragment loads (bank = 4*row + k, all distinct).
// ===========================================================================
#define TK        32
#define ROWB      144                  // 36 floats * 4B
#define ATILE_B   (128 * ROWB)         // 18432 B
#define STAGE_B   (2 * ATILE_B)        // A + B tile = 36864 B
#define GEMM_SMEM (2 * STAGE_B)        // 73728 B

__global__ __launch_bounds__(256) void gemm_mma_tf32(
    const float* __restrict__ A, const float* __restrict__ B,
    const float* __restrict__ bias, float* __restrict__ C,
    int M, int N, int K)
{
    extern __shared__ char smem[];
    const uint32_t sb = smem_u32(smem);
    const int tid    = threadIdx.x;
    const int wid    = tid >> 5;
    const int lane   = tid & 31;
    const int g      = lane >> 2;     // group id (row within tiles)
    const int tig    = lane & 3;      // thread in group
    const int warp_m = wid >> 1;      // 0..3
    const int warp_n = wid & 1;       // 0..1
    const int m0     = blockIdx.y * 128;
    const int n0     = blockIdx.x * 128;

    float c[2][8][4];
#pragma unroll
    for (int mt = 0; mt < 2; mt++)
#pragma unroll
        for (int nt = 0; nt < 8; nt++)
#pragma unroll
            for (int r = 0; r < 4; r++) c[mt][nt][r] = 0.0f;

    auto load_tile = [&](int slot, int k0) {
        const uint32_t aB = sb + slot * STAGE_B;
        const uint32_t bB = aB + ATILE_B;
#pragma unroll
        for (int i = 0; i < 4; i++) {
            const int idx = i * 256 + tid;   // [0,1024)
            const int row = idx >> 3;
            const int seg = idx & 7;
            cp16(aB + row * ROWB + seg * 16, A + (size_t)(m0 + row) * K + k0 + seg * 4);
            cp16(bB + row * ROWB + seg * 16, B + (size_t)(n0 + row) * K + k0 + seg * 4);
        }
        CP_COMMIT();
    };

    const int NT = K / TK;
    load_tile(0, 0);

    for (int t = 0; t < NT; t++) {
        if (t + 1 < NT) {
            load_tile((t + 1) & 1, (t + 1) * TK);
            CP_WAIT(1);
        } else {
            CP_WAIT(0);
        }
        __syncthreads();

        const uint32_t aB = sb + (t & 1) * STAGE_B;
        const uint32_t bB = aB + ATILE_B;

#pragma unroll
        for (int kk = 0; kk < TK; kk += 8) {
            uint32_t af[2][4];
            uint32_t bf[8][2];
#pragma unroll
            for (int mt = 0; mt < 2; mt++) {
                const int row = warp_m * 32 + mt * 16;
                af[mt][0] = lds32(aB + (row + g)     * ROWB + (kk + tig)     * 4);
                af[mt][1] = lds32(aB + (row + 8 + g) * ROWB + (kk + tig)     * 4);
                af[mt][2] = lds32(aB + (row + g)     * ROWB + (kk + tig + 4) * 4);
                af[mt][3] = lds32(aB + (row + 8 + g) * ROWB + (kk + tig + 4) * 4);
            }
#pragma unroll
            for (int nt = 0; nt < 8; nt++) {
                const int col = warp_n * 64 + nt * 8 + g;
                bf[nt][0] = lds32(bB + col * ROWB + (kk + tig)     * 4);
                bf[nt][1] = lds32(bB + col * ROWB + (kk + tig + 4) * 4);
            }
#pragma unroll
            for (int mt = 0; mt < 2; mt++)
#pragma unroll
                for (int nt = 0; nt < 8; nt++)
                    mma_16n8k8(c[mt][nt], af[mt], bf[nt]);
        }
        __syncthreads();
    }

    // epilogue: write C + bias (float2 per fragment row)
#pragma unroll
    for (int mt = 0; mt < 2; mt++) {
        const int row = m0 + warp_m * 32 + mt * 16 + g;
#pragma unroll
        for (int nt = 0; nt < 8; nt++) {
            const int col = n0 + warp_n * 64 + nt * 8 + tig * 2;
            const float bx = bias[col];
            const float by = bias[col + 1];
            float2 v0 = make_float2(c[mt][nt][0] + bx, c[mt][nt][1] + by);
            float2 v1 = make_float2(c[mt][nt][2] + bx, c[mt][nt][3] + by);
            *(float2*)(C + (size_t)row * N + col)       = v0;
            *(float2*)(C + (size_t)(row + 8) * N + col) = v1;
        }
    }
}

// ===========================================================================
// Flash attention (unchanged from R1), fp32, online softmax.
// ===========================================================================
#define QS_LD 65
#define VS_LD 68
#define SM_QS 0
#define SM_KS (SM_QS + 64 * QS_LD)
#define SM_VS (SM_KS + 64 * QS_LD)
#define SM_ST (SM_VS + 64 * VS_LD)
#define SM_M  (SM_ST + 64 * VS_LD)
#define SM_L  (SM_M + 64)
#define SM_AL (SM_L + 64)
#define SM_TOTAL (SM_AL + 64)

__global__ __launch_bounds__(256) void flash_attn(
    const float* __restrict__ qkv, float* __restrict__ out)
{
    extern __shared__ float sm[];
    float* Qs = sm + SM_QS;
    float* Ks = sm + SM_KS;
    float* Vs = sm + SM_VS;
    float* St = sm + SM_ST;
    float* m_s = sm + SM_M;
    float* l_s = sm + SM_L;
    float* al_s = sm + SM_AL;

    const int tid = threadIdx.x;
    const int tx  = tid & 15;
    const int ty  = tid >> 4;
    const int qt  = blockIdx.x;
    const int h   = blockIdx.y;
    const int b   = blockIdx.z;
    const int q0  = qt * 64;
    const float scale = 0.03125f;  // 1024^-0.5

    const float* qb = qkv + (size_t)b * SEQ * QKVDIM + (size_t)h * HDIM;
    const float* kb = qb + DIM;
    const float* vb = qb + 2 * DIM;

    for (int idx = tid; idx < 64 * 64; idx += 256) {
        const int d = idx & 63;
        const int r = idx >> 6;
        Qs[r * QS_LD + d] = qb[(size_t)(q0 + r) * QKVDIM + d];
    }
    if (tid < 64) { m_s[tid] = -1e30f; l_s[tid] = 0.0f; }

    float o_acc[4][4];
#pragma unroll
    for (int i = 0; i < 4; i++)
#pragma unroll
        for (int j = 0; j < 4; j++) o_acc[i][j] = 0.0f;

    for (int jt = 0; jt < SEQ / 64; jt++) {
        const int j0 = jt * 64;
        __syncthreads();
        for (int idx = tid; idx < 64 * 64; idx += 256) {
            const int d = idx & 63;
            const int cc = idx >> 6;
            Ks[cc * QS_LD + d] = kb[(size_t)(j0 + cc) * QKVDIM + d];
            Vs[cc * VS_LD + d] = vb[(size_t)(j0 + cc) * QKVDIM + d];
        }
        __syncthreads();

        float s[4][4];
#pragma unroll
        for (int i = 0; i < 4; i++)
#pragma unroll
            for (int j = 0; j < 4; j++) s[i][j] = 0.0f;

        for (int d = 0; d < 64; d++) {
            float qv[4], kv[4];
#pragma unroll
            for (int i = 0; i < 4; i++) qv[i] = Qs[(ty * 4 + i) * QS_LD + d];
#pragma unroll
            for (int j = 0; j < 4; j++) kv[j] = Ks[(tx * 4 + j) * QS_LD + d];
#pragma unroll
            for (int i = 0; i < 4; i++)
#pragma unroll
                for (int j = 0; j < 4; j++)
                    s[i][j] += qv[i] * kv[j];
        }
#pragma unroll
        for (int i = 0; i < 4; i++)
#pragma unroll
            for (int j = 0; j < 4; j++)
                St[(tx * 4 + j) * VS_LD + (ty * 4 + i)] = s[i][j] * scale;
        __syncthreads();

        if (tid < 64) {
            const int r = tid;
            const float m_old = m_s[r];
            float mx = m_old;
#pragma unroll 8
            for (int cc = 0; cc < 64; cc++)
                mx = fmaxf(mx, St[cc * VS_LD + r]);
            const float alpha = __expf(m_old - mx);
            float sum = 0.0f;
#pragma unroll 8
            for (int cc = 0; cc < 64; cc++) {
                const float p = __expf(St[cc * VS_LD + r] - mx);
                St[cc * VS_LD + r] = p;
                sum += p;
            }
            l_s[r] = l_s[r] * alpha + sum;
            m_s[r] = mx;
            al_s[r] = alpha;
        }
        __syncthreads();

        float a_i[4];
#pragma unroll
        for (int i = 0; i < 4; i++) a_i[i] = al_s[ty * 4 + i];
#pragma unroll
        for (int i = 0; i < 4; i++)
#pragma unroll
            for (int j = 0; j < 4; j++) o_acc[i][j] *= a_i[i];

        for (int j = 0; j < 64; j++) {
            float pv[4], vv[4];
            *(float4*)pv = *(const float4*)&St[j * VS_LD + ty * 4];
            *(float4*)vv = *(const float4*)&Vs[j * VS_LD + tx * 4];
#pragma unroll
            for (int i = 0; i < 4; i++)
#pragma unroll
                for (int k = 0; k < 4; k++)
                    o_acc[i][k] += pv[i] * vv[k];
        }
    }

    __syncthreads();
#pragma unroll
    for (int i = 0; i < 4; i++) {
        const int r = ty * 4 + i;
        const float inv_l = 1.0f / l_s[r];
        const size_t row = (size_t)b * SEQ + q0 + r;
#pragma unroll
        for (int k = 0; k < 4; k++) {
            out[row * DIM + h * HDIM + tx * 4 + k] = o_acc[i][k] * inv_l;
        }
    }
}

// ===========================================================================
// Launch
// ===========================================================================
extern "C" void kernel_launch(void* const* d_in, const int* in_sizes, int n_in,
                              void* d_out, int out_size)
{
    const float* x    = (const float*)d_in[0];
    const float* Wqkv = (const float*)d_in[1];
    const float* bqkv = (const float*)d_in[2];
    const float* W1   = (const float*)d_in[3];
    const float* b1   = (const float*)d_in[4];
    float* out = (float*)d_out;

    float *qkv_p, *attn_p, *xr_p, *wr_p, *w1r_p;
    cudaGetSymbolAddress((void**)&qkv_p,  g_qkv);
    cudaGetSymbolAddress((void**)&attn_p, g_attn);
    cudaGetSymbolAddress((void**)&xr_p,   g_xr);
    cudaGetSymbolAddress((void**)&wr_p,   g_wr);
    cudaGetSymbolAddress((void**)&w1r_p,  g_w1r);

    cudaFuncSetAttribute(gemm_mma_tf32,
                         cudaFuncAttributeMaxDynamicSharedMemorySize, GEMM_SMEM);
    cudaFuncSetAttribute(flash_attn,
                         cudaFuncAttributeMaxDynamicSharedMemorySize,
                         SM_TOTAL * (int)sizeof(float));

    // 0) round GEMM operands to tf32 grid (rna) so HMMA truncation is exact
    round_tf32<<<(ROWS * DIM / 4 + 255) / 256, 256>>>(x, xr_p, ROWS * DIM / 4);
    round_tf32<<<(QKVDIM * DIM / 4 + 255) / 256, 256>>>(Wqkv, wr_p, QKVDIM * DIM / 4);
    round_tf32<<<(DIM * DIM / 4 + 255) / 256, 256>>>(W1, w1r_p, DIM * DIM / 4);

    // 1) QKV projection on tensor cores (mma.sync tf32)
    {
        dim3 grid(QKVDIM / 128, ROWS / 128);
        gemm_mma_tf32<<<grid, 256, GEMM_SMEM>>>(xr_p, wr_p, bqkv, qkv_p,
                                                ROWS, QKVDIM, DIM);
    }

    // 2) Flash attention (SIMT)
    {
        dim3 grid(SEQ / 64, HEADS, BATCH);
        flash_attn<<<grid, 256, SM_TOTAL * (int)sizeof(float)>>>(qkv_p, attn_p);
    }

    // 2b) round attention output for the tf32 projection
    round_tf32<<<(ROWS * DIM / 4 + 255) / 256, 256>>>(attn_p, attn_p, ROWS * DIM / 4);

    // 3) Output projection on tensor cores (mma.sync tf32)
    {
        dim3 grid(DIM / 128, ROWS / 128);
        gemm_mma_tf32<<<grid, 256, GEMM_SMEM>>>(attn_p, w1r_p, b1, out,
                                                ROWS, DIM, DIM);
    }
}

// round 5
// speedup vs baseline: 3.6394x; 2.0819x over previous
#include <cuda_runtime.h>
#include <cuda_bf16.h>
#include <cstdint>

// ---------------------------------------------------------------------------
// Fused transformer block, fp32 in/out. All heavy math on mma.sync tf32.
//   qkv = x @ Wqkv^T + bqkv   (4096x3072x1024)  HMMA, epilogue tf32-rounds
//   attention: 16 heads, d=64, scale 1/32       HMMA flash attention
//   out = attn @ W1^T + b1    (4096x1024x1024)  HMMA
// ---------------------------------------------------------------------------

#define BATCH   4
#define SEQ     1024
#define DIM     1024
#define HEADS   16
#define HDIM    64
#define ROWS    (BATCH * SEQ)      // 4096
#define QKVDIM  (3 * DIM)          // 3072

__device__ __align__(256) float g_qkv[ROWS * QKVDIM];   // tf32-valued
__device__ __align__(256) float g_attn[ROWS * DIM];     // tf32-valued
__device__ __align__(256) float g_xr[ROWS * DIM];
__device__ __align__(256) float g_wr[QKVDIM * DIM];
__device__ __align__(256) float g_w1r[DIM * DIM];

// ===========================================================================
// helpers
// ===========================================================================
__device__ __forceinline__ uint32_t smem_u32(const void* p) {
    uint32_t a;
    asm("{ .reg .u64 t; cvta.to.shared.u64 t, %1; cvt.u32.u64 %0, t; }"
        : "=r"(a) : "l"(p));
    return a;
}
__device__ __forceinline__ uint32_t lds32(uint32_t addr) {
    uint32_t v;
    asm volatile("ld.shared.b32 %0, [%1];" : "=r"(v) : "r"(addr));
    return v;
}
__device__ __forceinline__ float ldsf(uint32_t addr) {
    float v;
    asm volatile("ld.shared.f32 %0, [%1];" : "=f"(v) : "r"(addr));
    return v;
}
__device__ __forceinline__ void cp16(uint32_t dst, const void* src) {
    asm volatile("cp.async.cg.shared.global [%0], [%1], 16;" :: "r"(dst), "l"(src));
}
#define CP_COMMIT() asm volatile("cp.async.commit_group;" ::: "memory")
#define CP_WAIT(n)  asm volatile("cp.async.wait_group %0;" :: "n"(n) : "memory")

__device__ __forceinline__ float rna_tf32(float x) {
    uint32_t u;
    asm("cvt.rna.tf32.f32 %0, %1;" : "=r"(u) : "f"(x));
    return __uint_as_float(u);
}

// m16n8k8 tf32 mma: D += A*B (row.col)
__device__ __forceinline__ void mma_16n8k8(
    float* c, const uint32_t* a, const uint32_t* b)
{
    asm volatile(
        "mma.sync.aligned.m16n8k8.row.col.f32.tf32.tf32.f32 "
        "{%0,%1,%2,%3}, {%4,%5,%6,%7}, {%8,%9}, {%0,%1,%2,%3};"
        : "+f"(c[0]), "+f"(c[1]), "+f"(c[2]), "+f"(c[3])
        : "r"(a[0]), "r"(a[1]), "r"(a[2]), "r"(a[3]), "r"(b[0]), "r"(b[1]));
}

// ===========================================================================
// tf32 rounding kernel
// ===========================================================================
__global__ __launch_bounds__(256) void round_tf32(
    const float* __restrict__ in, float* __restrict__ out, int n4)
{
    int i = blockIdx.x * blockDim.x + threadIdx.x;
    if (i >= n4) return;
    float4 v = ((const float4*)in)[i];
    float4 o;
    o.x = rna_tf32(v.x); o.y = rna_tf32(v.y);
    o.z = rna_tf32(v.z); o.w = rna_tf32(v.w);
    ((float4*)out)[i] = o;
}

// ===========================================================================
// mma.sync tf32 NT GEMM + bias (unchanged from R3, passing):
// C = A @ B^T + bias.  128x128 tile, TK=32, double-buffered cp.async,
// 256 thr, warp grid 4x2, warp tile 32x64. Rows 32 floats @ stride 36 floats.
// ===========================================================================
#define TK        32
#define ROWB      144                  // 36 floats
#define ATILE_B   (128 * ROWB)
#define STAGE_B   (2 * ATILE_B)
#define GEMM_SMEM (2 * STAGE_B)        // 73728 B

template <bool ROUND_OUT>
__global__ __launch_bounds__(256) void gemm_mma_tf32(
    const float* __restrict__ A, const float* __restrict__ B,
    const float* __restrict__ bias, float* __restrict__ C,
    int M, int N, int K)
{
    extern __shared__ char smem[];
    const uint32_t sb = smem_u32(smem);
    const int tid    = threadIdx.x;
    const int wid    = tid >> 5;
    const int lane   = tid & 31;
    const int g      = lane >> 2;
    const int tig    = lane & 3;
    const int warp_m = wid >> 1;
    const int warp_n = wid & 1;
    const int m0     = blockIdx.y * 128;
    const int n0     = blockIdx.x * 128;

    float c[2][8][4];
#pragma unroll
    for (int mt = 0; mt < 2; mt++)
#pragma unroll
        for (int nt = 0; nt < 8; nt++)
#pragma unroll
            for (int r = 0; r < 4; r++) c[mt][nt][r] = 0.0f;

    auto load_tile = [&](int slot, int k0) {
        const uint32_t aB = sb + slot * STAGE_B;
        const uint32_t bB = aB + ATILE_B;
#pragma unroll
        for (int i = 0; i < 4; i++) {
            const int idx = i * 256 + tid;
            const int row = idx >> 3;
            const int seg = idx & 7;
            cp16(aB + row * ROWB + seg * 16, A + (size_t)(m0 + row) * K + k0 + seg * 4);
            cp16(bB + row * ROWB + seg * 16, B + (size_t)(n0 + row) * K + k0 + seg * 4);
        }
        CP_COMMIT();
    };

    const int NT = K / TK;
    load_tile(0, 0);

    for (int t = 0; t < NT; t++) {
        if (t + 1 < NT) {
            load_tile((t + 1) & 1, (t + 1) * TK);
            CP_WAIT(1);
        } else {
            CP_WAIT(0);
        }
        __syncthreads();

        const uint32_t aB = sb + (t & 1) * STAGE_B;
        const uint32_t bB = aB + ATILE_B;

#pragma unroll
        for (int kk = 0; kk < TK; kk += 8) {
            uint32_t af[2][4];
            uint32_t bf[8][2];
#pragma unroll
            for (int mt = 0; mt < 2; mt++) {
                const int row = warp_m * 32 + mt * 16;
                af[mt][0] = lds32(aB + (row + g)     * ROWB + (kk + tig)     * 4);
                af[mt][1] = lds32(aB + (row + 8 + g) * ROWB + (kk + tig)     * 4);
                af[mt][2] = lds32(aB + (row + g)     * ROWB + (kk + tig + 4) * 4);
                af[mt][3] = lds32(aB + (row + 8 + g) * ROWB + (kk + tig + 4) * 4);
            }
#pragma unroll
            for (int nt = 0; nt < 8; nt++) {
                const int col = warp_n * 64 + nt * 8 + g;
                bf[nt][0] = lds32(bB + col * ROWB + (kk + tig)     * 4);
                bf[nt][1] = lds32(bB + col * ROWB + (kk + tig + 4) * 4);
            }
#pragma unroll
            for (int mt = 0; mt < 2; mt++)
#pragma unroll
                for (int nt = 0; nt < 8; nt++)
                    mma_16n8k8(c[mt][nt], af[mt], bf[nt]);
        }
        __syncthreads();
    }

#pragma unroll
    for (int mt = 0; mt < 2; mt++) {
        const int row = m0 + warp_m * 32 + mt * 16 + g;
#pragma unroll
        for (int nt = 0; nt < 8; nt++) {
            const int col = n0 + warp_n * 64 + nt * 8 + tig * 2;
            const float bx = bias[col];
            const float by = bias[col + 1];
            float2 v0, v1;
            if (ROUND_OUT) {
                v0 = make_float2(rna_tf32(c[mt][nt][0] + bx), rna_tf32(c[mt][nt][1] + by));
                v1 = make_float2(rna_tf32(c[mt][nt][2] + bx), rna_tf32(c[mt][nt][3] + by));
            } else {
                v0 = make_float2(c[mt][nt][0] + bx, c[mt][nt][1] + by);
                v1 = make_float2(c[mt][nt][2] + bx, c[mt][nt][3] + by);
            }
            *(float2*)(C + (size_t)row * N + col)       = v0;
            *(float2*)(C + (size_t)(row + 8) * N + col) = v1;
        }
    }
}

// ===========================================================================
// Tensor-core flash attention (tf32 mma.sync).
// Block: 128 threads (4 warps), 64 q-rows (16 per warp). 64-key tiles,
// double-buffered cp.async K/V.
// Q/K: rows of 64 floats at stride 68 floats (272 B): 272 mod 128 = 16 ->
//      fragment-read banks 16g+4tig bytes mod 128, all 32 lanes distinct.
// V:   rows of 64 floats, stride 64, XOR swizzle col*4 ^ 32*(row&3):
//      frag-read banks g + 8*((nt^tig)&3), bijective over 32 lanes.
// ===========================================================================
#define FA_QK_STRIDE 272                         // bytes per row
#define FA_QS_OFF    0
#define FA_QS_BUF    (64 * FA_QK_STRIDE)         // 17408
#define FA_KS_OFF    FA_QS_BUF
#define FA_KS_BUF    (64 * FA_QK_STRIDE)         // 17408
#define FA_VS_OFF    (FA_KS_OFF + 2 * FA_KS_BUF) // 52224
#define FA_VS_BUF    (64 * 256)                  // 16384
#define FA_SMEM      (FA_VS_OFF + 2 * FA_VS_BUF) // 84992 B

__global__ __launch_bounds__(128) void flash_attn_tc(
    const float* __restrict__ qkv, float* __restrict__ out)
{
    extern __shared__ char smem[];
    const uint32_t sb = smem_u32(smem);
    const int tid  = threadIdx.x;
    const int wid  = tid >> 5;
    const int lane = tid & 31;
    const int g    = lane >> 2;
    const int tig  = lane & 3;
    const int q0   = blockIdx.x * 64;
    const int h    = blockIdx.y;
    const int b    = blockIdx.z;

    const float* qb = qkv + (size_t)b * SEQ * QKVDIM + (size_t)h * HDIM;
    const float* kb = qb + DIM;
    const float* vb = qb + 2 * DIM;

    // --- load Q tile (64 rows x 64 floats) ---
#pragma unroll
    for (int i = 0; i < 8; i++) {
        const int idx = i * 128 + tid;         // [0,1024)
        const int row = idx >> 4;
        const int seg = idx & 15;
        cp16(sb + FA_QS_OFF + row * FA_QK_STRIDE + seg * 16,
             qb + (size_t)(q0 + row) * QKVDIM + seg * 4);
    }
    CP_COMMIT();

    auto load_kv = [&](int slot, int jt) {
        const int j0 = jt * 64;
        const uint32_t kB = sb + FA_KS_OFF + slot * FA_KS_BUF;
        const uint32_t vB = sb + FA_VS_OFF + slot * FA_VS_BUF;
#pragma unroll
        for (int i = 0; i < 8; i++) {
            const int idx = i * 128 + tid;
            const int row = idx >> 4;
            const int seg = idx & 15;
            cp16(kB + row * FA_QK_STRIDE + seg * 16,
                 kb + (size_t)(j0 + row) * QKVDIM + seg * 4);
            cp16(vB + row * 256 + ((seg * 16) ^ ((row & 3) * 32)),
                 vb + (size_t)(j0 + row) * QKVDIM + seg * 4);
        }
        CP_COMMIT();
    };

    load_kv(0, 0);
    CP_WAIT(1);            // Q group done (KV0 may still be in flight)
    __syncthreads();

    // --- Q fragments, pre-scaled by 1/32 (exact power of two in tf32) ---
    uint32_t qf[8][4];
    {
        const uint32_t r0 = sb + FA_QS_OFF + (wid * 16 + g) * FA_QK_STRIDE;
        const uint32_t r8 = r0 + 8 * FA_QK_STRIDE;
#pragma unroll
        for (int ks = 0; ks < 8; ks++) {
            qf[ks][0] = __float_as_uint(ldsf(r0 + (ks * 8 + tig)     * 4) * 0.03125f);
            qf[ks][1] = __float_as_uint(ldsf(r8 + (ks * 8 + tig)     * 4) * 0.03125f);
            qf[ks][2] = __float_as_uint(ldsf(r0 + (ks * 8 + tig + 4) * 4) * 0.03125f);
            qf[ks][3] = __float_as_uint(ldsf(r8 + (ks * 8 + tig + 4) * 4) * 0.03125f);
        }
    }

    float o[8][4];
#pragma unroll
    for (int nt = 0; nt < 8; nt++)
#pragma unroll
        for (int r = 0; r < 4; r++) o[nt][r] = 0.0f;
    float m_r[2] = {-1e30f, -1e30f};
    float l_r[2] = {0.0f, 0.0f};

    const int s0  = tig >> 1;
    const int sel = tig & 1;
    const uint32_t vswz = tig * 32;   // XOR term, row&3 == tig for frag rows

    for (int jt = 0; jt < SEQ / 64; jt++) {
        if (jt + 1 < SEQ / 64) {
            load_kv((jt + 1) & 1, jt + 1);
            CP_WAIT(1);
        } else {
            CP_WAIT(0);
        }
        __syncthreads();

        const uint32_t kB = sb + FA_KS_OFF + (jt & 1) * FA_KS_BUF;
        const uint32_t vB = sb + FA_VS_OFF + (jt & 1) * FA_VS_BUF;

        // --- S = (Q/32) @ K^T ---
        float c[8][4];
#pragma unroll
        for (int nt = 0; nt < 8; nt++)
#pragma unroll
            for (int r = 0; r < 4; r++) c[nt][r] = 0.0f;

#pragma unroll
        for (int ks = 0; ks < 8; ks++) {
            uint32_t bf[8][2];
#pragma unroll
            for (int nt = 0; nt < 8; nt++) {
                const uint32_t base =
                    kB + (nt * 8 + g) * FA_QK_STRIDE + (ks * 8 + tig) * 4;
                bf[nt][0] = lds32(base);
                bf[nt][1] = lds32(base + 16);
            }
#pragma unroll
            for (int nt = 0; nt < 8; nt++)
                mma_16n8k8(c[nt], qf[ks], bf[nt]);
        }

        // --- online softmax (per thread: rows g and g+8 of its warp tile) ---
#pragma unroll
        for (int r = 0; r < 2; r++) {
            float mx = -1e30f;
#pragma unroll
            for (int nt = 0; nt < 8; nt++) {
                mx = fmaxf(mx, c[nt][2 * r]);
                mx = fmaxf(mx, c[nt][2 * r + 1]);
            }
            mx = fmaxf(mx, __shfl_xor_sync(0xffffffffu, mx, 1));
            mx = fmaxf(mx, __shfl_xor_sync(0xffffffffu, mx, 2));
            const float mnew  = fmaxf(m_r[r], mx);
            const float alpha = __expf(m_r[r] - mnew);
            float sum = 0.0f;
#pragma unroll
            for (int nt = 0; nt < 8; nt++) {
                const float p0 = __expf(c[nt][2 * r]     - mnew);
                const float p1 = __expf(c[nt][2 * r + 1] - mnew);
                c[nt][2 * r] = p0; c[nt][2 * r + 1] = p1;
                sum += p0 + p1;
            }
            sum += __shfl_xor_sync(0xffffffffu, sum, 1);
            sum += __shfl_xor_sync(0xffffffffu, sum, 2);
            l_r[r] = l_r[r] * alpha + sum;
            m_r[r] = mnew;
#pragma unroll
            for (int nt = 0; nt < 8; nt++) {
                o[nt][2 * r]     *= alpha;
                o[nt][2 * r + 1] *= alpha;
            }
        }

        // --- round P to tf32 grid ---
#pragma unroll
        for (int nt = 0; nt < 8; nt++)
#pragma unroll
            for (int r = 0; r < 4; r++) c[nt][r] = rna_tf32(c[nt][r]);

        // --- O += P @ V  (P C-frag -> A-frag via quad shuffles) ---
#pragma unroll
        for (int ks = 0; ks < 8; ks++) {
            const float x0  = __shfl_sync(0xffffffffu, c[ks][0], s0, 4);
            const float x1  = __shfl_sync(0xffffffffu, c[ks][1], s0, 4);
            const float y0  = __shfl_sync(0xffffffffu, c[ks][2], s0, 4);
            const float y1  = __shfl_sync(0xffffffffu, c[ks][3], s0, 4);
            const float x0b = __shfl_sync(0xffffffffu, c[ks][0], s0 + 2, 4);
            const float x1b = __shfl_sync(0xffffffffu, c[ks][1], s0 + 2, 4);
            const float y0b = __shfl_sync(0xffffffffu, c[ks][2], s0 + 2, 4);
            const float y1b = __shfl_sync(0xffffffffu, c[ks][3], s0 + 2, 4);
            uint32_t pa[4];
            pa[0] = __float_as_uint(sel ? x1  : x0);
            pa[1] = __float_as_uint(sel ? y1  : y0);
            pa[2] = __float_as_uint(sel ? x1b : x0b);
            pa[3] = __float_as_uint(sel ? y1b : y0b);

            uint32_t vf[8][2];
            const uint32_t vr0 = vB + (ks * 8 + tig) * 256;      // row ks*8+tig
            const uint32_t vr4 = vB + (ks * 8 + tig + 4) * 256;  // row ks*8+tig+4
#pragma unroll
            for (int nt = 0; nt < 8; nt++) {
                const uint32_t coff = ((nt * 8 + g) * 4) ^ vswz;
                vf[nt][0] = lds32(vr0 + coff);
                vf[nt][1] = lds32(vr4 + coff);
            }
#pragma unroll
            for (int nt = 0; nt < 8; nt++)
                mma_16n8k8(o[nt], pa, vf[nt]);
        }
        __syncthreads();
    }

    // --- epilogue: O /= l, round to tf32 (feeds proj GEMM), store ---
    const float inv0 = 1.0f / l_r[0];
    const float inv1 = 1.0f / l_r[1];
    const size_t row0 = (size_t)b * SEQ + q0 + wid * 16 + g;
    const size_t row1 = row0 + 8;
#pragma unroll
    for (int nt = 0; nt < 8; nt++) {
        const int col = h * HDIM + nt * 8 + 2 * tig;
        float2 v0 = make_float2(rna_tf32(o[nt][0] * inv0), rna_tf32(o[nt][1] * inv0));
        float2 v1 = make_float2(rna_tf32(o[nt][2] * inv1), rna_tf32(o[nt][3] * inv1));
        *(float2*)(out + row0 * DIM + col) = v0;
        *(float2*)(out + row1 * DIM + col) = v1;
    }
}

// ===========================================================================
// Launch
// ===========================================================================
extern "C" void kernel_launch(void* const* d_in, const int* in_sizes, int n_in,
                              void* d_out, int out_size)
{
    const float* x    = (const float*)d_in[0];
    const float* Wqkv = (const float*)d_in[1];
    const float* bqkv = (const float*)d_in[2];
    const float* W1   = (const float*)d_in[3];
    const float* b1   = (const float*)d_in[4];
    float* out = (float*)d_out;

    float *qkv_p, *attn_p, *xr_p, *wr_p, *w1r_p;
    cudaGetSymbolAddress((void**)&qkv_p,  g_qkv);
    cudaGetSymbolAddress((void**)&attn_p, g_attn);
    cudaGetSymbolAddress((void**)&xr_p,   g_xr);
    cudaGetSymbolAddress((void**)&wr_p,   g_wr);
    cudaGetSymbolAddress((void**)&w1r_p,  g_w1r);

    cudaFuncSetAttribute(gemm_mma_tf32<true>,
                         cudaFuncAttributeMaxDynamicSharedMemorySize, GEMM_SMEM);
    cudaFuncSetAttribute(gemm_mma_tf32<false>,
                         cudaFuncAttributeMaxDynamicSharedMemorySize, GEMM_SMEM);
    cudaFuncSetAttribute(flash_attn_tc,
                         cudaFuncAttributeMaxDynamicSharedMemorySize, FA_SMEM);

    // 0) round GEMM operands to tf32 grid
    round_tf32<<<(ROWS * DIM / 4 + 255) / 256, 256>>>(x, xr_p, ROWS * DIM / 4);
    round_tf32<<<(QKVDIM * DIM / 4 + 255) / 256, 256>>>(Wqkv, wr_p, QKVDIM * DIM / 4);
    round_tf32<<<(DIM * DIM / 4 + 255) / 256, 256>>>(W1, w1r_p, DIM * DIM / 4);

    // 1) QKV projection (epilogue rounds -> attention inputs are tf32-exact)
    {
        dim3 grid(QKVDIM / 128, ROWS / 128);
        gemm_mma_tf32<true><<<grid, 256, GEMM_SMEM>>>(xr_p, wr_p, bqkv, qkv_p,
                                                      ROWS, QKVDIM, DIM);
    }

    // 2) Tensor-core flash attention (epilogue rounds -> proj A is tf32-exact)
    {
        dim3 grid(SEQ / 64, HEADS, BATCH);
        flash_attn_tc<<<grid, 128, FA_SMEM>>>(qkv_p, attn_p);
    }

    // 3) Output projection (final output, unrounded)
    {
        dim3 grid(DIM / 128, ROWS / 128);
        gemm_mma_tf32<false><<<grid, 256, GEMM_SMEM>>>(attn_p, w1r_p, b1, out,
                                                       ROWS, DIM, DIM);
    }
}

// round 6
// speedup vs baseline: 3.6440x; 1.0013x over previous
#include <cuda_runtime.h>
#include <cuda_bf16.h>
#include <cstdint>

// ---------------------------------------------------------------------------
// Fused transformer block, fp32 in/out. All heavy math on mma.sync tf32.
//   qkv = x @ Wqkv^T + bqkv   (4096x3072x1024)  HMMA, epilogue tf32-rounds
//   attention: 16 heads, d=64, scale 1/32       HMMA flash attention
//   out = attn @ W1^T + b1    (4096x1024x1024)  HMMA
// ---------------------------------------------------------------------------

#define BATCH   4
#define SEQ     1024
#define DIM     1024
#define HEADS   16
#define HDIM    64
#define ROWS    (BATCH * SEQ)      // 4096
#define QKVDIM  (3 * DIM)          // 3072

__device__ __align__(256) float g_qkv[ROWS * QKVDIM];   // tf32-valued
__device__ __align__(256) float g_attn[ROWS * DIM];     // tf32-valued
__device__ __align__(256) float g_xr[ROWS * DIM];
__device__ __align__(256) float g_wr[QKVDIM * DIM];
__device__ __align__(256) float g_w1r[DIM * DIM];

// ===========================================================================
// helpers
// ===========================================================================
__device__ __forceinline__ uint32_t smem_u32(const void* p) {
    uint32_t a;
    asm("{ .reg .u64 t; cvta.to.shared.u64 t, %1; cvt.u32.u64 %0, t; }"
        : "=r"(a) : "l"(p));
    return a;
}
__device__ __forceinline__ uint32_t lds32(uint32_t addr) {
    uint32_t v;
    asm volatile("ld.shared.b32 %0, [%1];" : "=r"(v) : "r"(addr));
    return v;
}
__device__ __forceinline__ float ldsf(uint32_t addr) {
    float v;
    asm volatile("ld.shared.f32 %0, [%1];" : "=f"(v) : "r"(addr));
    return v;
}
__device__ __forceinline__ void cp16(uint32_t dst, const void* src) {
    asm volatile("cp.async.cg.shared.global [%0], [%1], 16;" :: "r"(dst), "l"(src));
}
#define CP_COMMIT() asm volatile("cp.async.commit_group;" ::: "memory")
#define CP_WAIT(n)  asm volatile("cp.async.wait_group %0;" :: "n"(n) : "memory")

__device__ __forceinline__ float rna_tf32(float x) {
    uint32_t u;
    asm("cvt.rna.tf32.f32 %0, %1;" : "=r"(u) : "f"(x));
    return __uint_as_float(u);
}

// m16n8k8 tf32 mma: D += A*B (row.col)
__device__ __forceinline__ void mma_16n8k8(
    float* c, const uint32_t* a, const uint32_t* b)
{
    asm volatile(
        "mma.sync.aligned.m16n8k8.row.col.f32.tf32.tf32.f32 "
        "{%0,%1,%2,%3}, {%4,%5,%6,%7}, {%8,%9}, {%0,%1,%2,%3};"
        : "+f"(c[0]), "+f"(c[1]), "+f"(c[2]), "+f"(c[3])
        : "r"(a[0]), "r"(a[1]), "r"(a[2]), "r"(a[3]), "r"(b[0]), "r"(b[1]));
}

// ===========================================================================
// tf32 rounding kernel
// ===========================================================================
__global__ __launch_bounds__(256) void round_tf32(
    const float* __restrict__ in, float* __restrict__ out, int n4)
{
    int i = blockIdx.x * blockDim.x + threadIdx.x;
    if (i >= n4) return;
    float4 v = ((const float4*)in)[i];
    float4 o;
    o.x = rna_tf32(v.x); o.y = rna_tf32(v.y);
    o.z = rna_tf32(v.z); o.w = rna_tf32(v.w);
    ((float4*)out)[i] = o;
}

// ===========================================================================
// mma.sync tf32 NT GEMM + bias:  C = A @ B^T + bias.
// 128x128 CTA tile, TK=32, 4-stage cp.async pipeline, ONE sync per K-tile.
// 256 thr, warp grid 4x2, warp tile 32x64. Rows 32 floats @ stride 36 floats.
// ===========================================================================
#define TK        32
#define ROWB      144                  // 36 floats
#define ATILE_B   (128 * ROWB)
#define STAGE_B   (2 * ATILE_B)        // 36864
#define GSTAGES   4
#define GEMM_SMEM (GSTAGES * STAGE_B)  // 147456 B

template <bool ROUND_OUT>
__global__ __launch_bounds__(256) void gemm_mma_tf32(
    const float* __restrict__ A, const float* __restrict__ B,
    const float* __restrict__ bias, float* __restrict__ C,
    int M, int N, int K)
{
    extern __shared__ char smem[];
    const uint32_t sb = smem_u32(smem);
    const int tid    = threadIdx.x;
    const int wid    = tid >> 5;
    const int lane   = tid & 31;
    const int g      = lane >> 2;
    const int tig    = lane & 3;
    const int warp_m = wid >> 1;
    const int warp_n = wid & 1;
    const int m0     = blockIdx.y * 128;
    const int n0     = blockIdx.x * 128;

    float c[2][8][4];
#pragma unroll
    for (int mt = 0; mt < 2; mt++)
#pragma unroll
        for (int nt = 0; nt < 8; nt++)
#pragma unroll
            for (int r = 0; r < 4; r++) c[mt][nt][r] = 0.0f;

    auto load_tile = [&](int slot, int k0) {
        const uint32_t aB = sb + slot * STAGE_B;
        const uint32_t bB = aB + ATILE_B;
#pragma unroll
        for (int i = 0; i < 4; i++) {
            const int idx = i * 256 + tid;
            const int row = idx >> 3;
            const int seg = idx & 7;
            cp16(aB + row * ROWB + seg * 16, A + (size_t)(m0 + row) * K + k0 + seg * 4);
            cp16(bB + row * ROWB + seg * 16, B + (size_t)(n0 + row) * K + k0 + seg * 4);
        }
        CP_COMMIT();
    };

    const int NT = K / TK;
    // prologue: 3 tiles in flight
    load_tile(0, 0);
    load_tile(1, TK);
    load_tile(2, 2 * TK);

    for (int t = 0; t < NT; t++) {
        CP_WAIT(2);            // tile t's group complete (t+1, t+2 may pend)
        __syncthreads();       // all threads' tile-t data visible; also WAR
                               // guard: nobody still reads slot (t-1)%4
        if (t + 3 < NT)
            load_tile((t + 3) & (GSTAGES - 1), (t + 3) * TK);

        const uint32_t aB = sb + (t & (GSTAGES - 1)) * STAGE_B;
        const uint32_t bB = aB + ATILE_B;

#pragma unroll
        for (int kk = 0; kk < TK; kk += 8) {
            uint32_t af[2][4];
            uint32_t bf[8][2];
#pragma unroll
            for (int mt = 0; mt < 2; mt++) {
                const int row = warp_m * 32 + mt * 16;
                af[mt][0] = lds32(aB + (row + g)     * ROWB + (kk + tig)     * 4);
                af[mt][1] = lds32(aB + (row + 8 + g) * ROWB + (kk + tig)     * 4);
                af[mt][2] = lds32(aB + (row + g)     * ROWB + (kk + tig + 4) * 4);
                af[mt][3] = lds32(aB + (row + 8 + g) * ROWB + (kk + tig + 4) * 4);
            }
#pragma unroll
            for (int nt = 0; nt < 8; nt++) {
                const int col = warp_n * 64 + nt * 8 + g;
                bf[nt][0] = lds32(bB + col * ROWB + (kk + tig)     * 4);
                bf[nt][1] = lds32(bB + col * ROWB + (kk + tig + 4) * 4);
            }
#pragma unroll
            for (int mt = 0; mt < 2; mt++)
#pragma unroll
                for (int nt = 0; nt < 8; nt++)
                    mma_16n8k8(c[mt][nt], af[mt], bf[nt]);
        }
        // no trailing sync: next iteration's top barrier provides it
    }

#pragma unroll
    for (int mt = 0; mt < 2; mt++) {
        const int row = m0 + warp_m * 32 + mt * 16 + g;
#pragma unroll
        for (int nt = 0; nt < 8; nt++) {
            const int col = n0 + warp_n * 64 + nt * 8 + tig * 2;
            const float bx = bias[col];
            const float by = bias[col + 1];
            float2 v0, v1;
            if (ROUND_OUT) {
                v0 = make_float2(rna_tf32(c[mt][nt][0] + bx), rna_tf32(c[mt][nt][1] + by));
                v1 = make_float2(rna_tf32(c[mt][nt][2] + bx), rna_tf32(c[mt][nt][3] + by));
            } else {
                v0 = make_float2(c[mt][nt][0] + bx, c[mt][nt][1] + by);
                v1 = make_float2(c[mt][nt][2] + bx, c[mt][nt][3] + by);
            }
            *(float2*)(C + (size_t)row * N + col)       = v0;
            *(float2*)(C + (size_t)(row + 8) * N + col) = v1;
        }
    }
}

// ===========================================================================
// Tensor-core flash attention (tf32 mma.sync), unchanged from R5 (passing).
// ===========================================================================
#define FA_QK_STRIDE 272
#define FA_QS_OFF    0
#define FA_QS_BUF    (64 * FA_QK_STRIDE)
#define FA_KS_OFF    FA_QS_BUF
#define FA_KS_BUF    (64 * FA_QK_STRIDE)
#define FA_VS_OFF    (FA_KS_OFF + 2 * FA_KS_BUF)
#define FA_VS_BUF    (64 * 256)
#define FA_SMEM      (FA_VS_OFF + 2 * FA_VS_BUF)   // 84992 B

__global__ __launch_bounds__(128) void flash_attn_tc(
    const float* __restrict__ qkv, float* __restrict__ out)
{
    extern __shared__ char smem[];
    const uint32_t sb = smem_u32(smem);
    const int tid  = threadIdx.x;
    const int wid  = tid >> 5;
    const int lane = tid & 31;
    const int g    = lane >> 2;
    const int tig  = lane & 3;
    const int q0   = blockIdx.x * 64;
    const int h    = blockIdx.y;
    const int b    = blockIdx.z;

    const float* qb = qkv + (size_t)b * SEQ * QKVDIM + (size_t)h * HDIM;
    const float* kb = qb + DIM;
    const float* vb = qb + 2 * DIM;

#pragma unroll
    for (int i = 0; i < 8; i++) {
        const int idx = i * 128 + tid;
        const int row = idx >> 4;
        const int seg = idx & 15;
        cp16(sb + FA_QS_OFF + row * FA_QK_STRIDE + seg * 16,
             qb + (size_t)(q0 + row) * QKVDIM + seg * 4);
    }
    CP_COMMIT();

    auto load_kv = [&](int slot, int jt) {
        const int j0 = jt * 64;
        const uint32_t kB = sb + FA_KS_OFF + slot * FA_KS_BUF;
        const uint32_t vB = sb + FA_VS_OFF + slot * FA_VS_BUF;
#pragma unroll
        for (int i = 0; i < 8; i++) {
            const int idx = i * 128 + tid;
            const int row = idx >> 4;
            const int seg = idx & 15;
            cp16(kB + row * FA_QK_STRIDE + seg * 16,
                 kb + (size_t)(j0 + row) * QKVDIM + seg * 4);
            cp16(vB + row * 256 + ((seg * 16) ^ ((row & 3) * 32)),
                 vb + (size_t)(j0 + row) * QKVDIM + seg * 4);
        }
        CP_COMMIT();
    };

    load_kv(0, 0);
    CP_WAIT(1);
    __syncthreads();

    uint32_t qf[8][4];
    {
        const uint32_t r0 = sb + FA_QS_OFF + (wid * 16 + g) * FA_QK_STRIDE;
        const uint32_t r8 = r0 + 8 * FA_QK_STRIDE;
#pragma unroll
        for (int ks = 0; ks < 8; ks++) {
            qf[ks][0] = __float_as_uint(ldsf(r0 + (ks * 8 + tig)     * 4) * 0.03125f);
            qf[ks][1] = __float_as_uint(ldsf(r8 + (ks * 8 + tig)     * 4) * 0.03125f);
            qf[ks][2] = __float_as_uint(ldsf(r0 + (ks * 8 + tig + 4) * 4) * 0.03125f);
            qf[ks][3] = __float_as_uint(ldsf(r8 + (ks * 8 + tig + 4) * 4) * 0.03125f);
        }
    }

    float o[8][4];
#pragma unroll
    for (int nt = 0; nt < 8; nt++)
#pragma unroll
        for (int r = 0; r < 4; r++) o[nt][r] = 0.0f;
    float m_r[2] = {-1e30f, -1e30f};
    float l_r[2] = {0.0f, 0.0f};

    const int s0  = tig >> 1;
    const int sel = tig & 1;
    const uint32_t vswz = tig * 32;

    for (int jt = 0; jt < SEQ / 64; jt++) {
        if (jt + 1 < SEQ / 64) {
            load_kv((jt + 1) & 1, jt + 1);
            CP_WAIT(1);
        } else {
            CP_WAIT(0);
        }
        __syncthreads();

        const uint32_t kB = sb + FA_KS_OFF + (jt & 1) * FA_KS_BUF;
        const uint32_t vB = sb + FA_VS_OFF + (jt & 1) * FA_VS_BUF;

        float c[8][4];
#pragma unroll
        for (int nt = 0; nt < 8; nt++)
#pragma unroll
            for (int r = 0; r < 4; r++) c[nt][r] = 0.0f;

#pragma unroll
        for (int ks = 0; ks < 8; ks++) {
            uint32_t bf[8][2];
#pragma unroll
            for (int nt = 0; nt < 8; nt++) {
                const uint32_t base =
                    kB + (nt * 8 + g) * FA_QK_STRIDE + (ks * 8 + tig) * 4;
                bf[nt][0] = lds32(base);
                bf[nt][1] = lds32(base + 16);
            }
#pragma unroll
            for (int nt = 0; nt < 8; nt++)
                mma_16n8k8(c[nt], qf[ks], bf[nt]);
        }

#pragma unroll
        for (int r = 0; r < 2; r++) {
            float mx = -1e30f;
#pragma unroll
            for (int nt = 0; nt < 8; nt++) {
                mx = fmaxf(mx, c[nt][2 * r]);
                mx = fmaxf(mx, c[nt][2 * r + 1]);
            }
            mx = fmaxf(mx, __shfl_xor_sync(0xffffffffu, mx, 1));
            mx = fmaxf(mx, __shfl_xor_sync(0xffffffffu, mx, 2));
            const float mnew  = fmaxf(m_r[r], mx);
            const float alpha = __expf(m_r[r] - mnew);
            float sum = 0.0f;
#pragma unroll
            for (int nt = 0; nt < 8; nt++) {
                const float p0 = __expf(c[nt][2 * r]     - mnew);
                const float p1 = __expf(c[nt][2 * r + 1] - mnew);
                c[nt][2 * r] = p0; c[nt][2 * r + 1] = p1;
                sum += p0 + p1;
            }
            sum += __shfl_xor_sync(0xffffffffu, sum, 1);
            sum += __shfl_xor_sync(0xffffffffu, sum, 2);
            l_r[r] = l_r[r] * alpha + sum;
            m_r[r] = mnew;
#pragma unroll
            for (int nt = 0; nt < 8; nt++) {
                o[nt][2 * r]     *= alpha;
                o[nt][2 * r + 1] *= alpha;
            }
        }

#pragma unroll
        for (int nt = 0; nt < 8; nt++)
#pragma unroll
            for (int r = 0; r < 4; r++) c[nt][r] = rna_tf32(c[nt][r]);

#pragma unroll
        for (int ks = 0; ks < 8; ks++) {
            const float x0  = __shfl_sync(0xffffffffu, c[ks][0], s0, 4);
            const float x1  = __shfl_sync(0xffffffffu, c[ks][1], s0, 4);
            const float y0  = __shfl_sync(0xffffffffu, c[ks][2], s0, 4);
            const float y1  = __shfl_sync(0xffffffffu, c[ks][3], s0, 4);
            const float x0b = __shfl_sync(0xffffffffu, c[ks][0], s0 + 2, 4);
            const float x1b = __shfl_sync(0xffffffffu, c[ks][1], s0 + 2, 4);
            const float y0b = __shfl_sync(0xffffffffu, c[ks][2], s0 + 2, 4);
            const float y1b = __shfl_sync(0xffffffffu, c[ks][3], s0 + 2, 4);
            uint32_t pa[4];
            pa[0] = __float_as_uint(sel ? x1  : x0);
            pa[1] = __float_as_uint(sel ? y1  : y0);
            pa[2] = __float_as_uint(sel ? x1b : x0b);
            pa[3] = __float_as_uint(sel ? y1b : y0b);

            uint32_t vf[8][2];
            const uint32_t vr0 = vB + (ks * 8 + tig) * 256;
            const uint32_t vr4 = vB + (ks * 8 + tig + 4) * 256;
#pragma unroll
            for (int nt = 0; nt < 8; nt++) {
                const uint32_t coff = ((nt * 8 + g) * 4) ^ vswz;
                vf[nt][0] = lds32(vr0 + coff);
                vf[nt][1] = lds32(vr4 + coff);
            }
#pragma unroll
            for (int nt = 0; nt < 8; nt++)
                mma_16n8k8(o[nt], pa, vf[nt]);
        }
        __syncthreads();
    }

    const float inv0 = 1.0f / l_r[0];
    const float inv1 = 1.0f / l_r[1];
    const size_t row0 = (size_t)b * SEQ + q0 + wid * 16 + g;
    const size_t row1 = row0 + 8;
#pragma unroll
    for (int nt = 0; nt < 8; nt++) {
        const int col = h * HDIM + nt * 8 + 2 * tig;
        float2 v0 = make_float2(rna_tf32(o[nt][0] * inv0), rna_tf32(o[nt][1] * inv0));
        float2 v1 = make_float2(rna_tf32(o[nt][2] * inv1), rna_tf32(o[nt][3] * inv1));
        *(float2*)(out + row0 * DIM + col) = v0;
        *(float2*)(out + row1 * DIM + col) = v1;
    }
}

// ===========================================================================
// Launch
// ===========================================================================
extern "C" void kernel_launch(void* const* d_in, const int* in_sizes, int n_in,
                              void* d_out, int out_size)
{
    const float* x    = (const float*)d_in[0];
    const float* Wqkv = (const float*)d_in[1];
    const float* bqkv = (const float*)d_in[2];
    const float* W1   = (const float*)d_in[3];
    const float* b1   = (const float*)d_in[4];
    float* out = (float*)d_out;

    float *qkv_p, *attn_p, *xr_p, *wr_p, *w1r_p;
    cudaGetSymbolAddress((void**)&qkv_p,  g_qkv);
    cudaGetSymbolAddress((void**)&attn_p, g_attn);
    cudaGetSymbolAddress((void**)&xr_p,   g_xr);
    cudaGetSymbolAddress((void**)&wr_p,   g_wr);
    cudaGetSymbolAddress((void**)&w1r_p,  g_w1r);

    cudaFuncSetAttribute(gemm_mma_tf32<true>,
                         cudaFuncAttributeMaxDynamicSharedMemorySize, GEMM_SMEM);
    cudaFuncSetAttribute(gemm_mma_tf32<false>,
                         cudaFuncAttributeMaxDynamicSharedMemorySize, GEMM_SMEM);
    cudaFuncSetAttribute(flash_attn_tc,
                         cudaFuncAttributeMaxDynamicSharedMemorySize, FA_SMEM);

    // 0) round GEMM operands to tf32 grid
    round_tf32<<<(ROWS * DIM / 4 + 255) / 256, 256>>>(x, xr_p, ROWS * DIM / 4);
    round_tf32<<<(QKVDIM * DIM / 4 + 255) / 256, 256>>>(Wqkv, wr_p, QKVDIM * DIM / 4);
    round_tf32<<<(DIM * DIM / 4 + 255) / 256, 256>>>(W1, w1r_p, DIM * DIM / 4);

    // 1) QKV projection (epilogue rounds -> attention inputs are tf32-exact)
    {
        dim3 grid(QKVDIM / 128, ROWS / 128);
        gemm_mma_tf32<true><<<grid, 256, GEMM_SMEM>>>(xr_p, wr_p, bqkv, qkv_p,
                                                      ROWS, QKVDIM, DIM);
    }

    // 2) Tensor-core flash attention
    {
        dim3 grid(SEQ / 64, HEADS, BATCH);
        flash_attn_tc<<<grid, 128, FA_SMEM>>>(qkv_p, attn_p);
    }

    // 3) Output projection (final output, unrounded)
    {
        dim3 grid(DIM / 128, ROWS / 128);
        gemm_mma_tf32<false><<<grid, 256, GEMM_SMEM>>>(attn_p, w1r_p, b1, out,
                                                       ROWS, DIM, DIM);
    }
}

// round 7
// speedup vs baseline: 3.8959x; 1.0691x over previous
#include <cuda_runtime.h>
#include <cuda_bf16.h>
#include <cstdint>

// ---------------------------------------------------------------------------
// Fused transformer block, fp32 in/out. All heavy math on mma.sync tf32.
//   qkv = x @ Wqkv^T + bqkv   (4096x3072x1024)  HMMA, epilogue tf32-rounds
//   attention: 16 heads, d=64, scale 1/32       HMMA flash attention
//   out = attn @ W1^T + b1    (4096x1024x1024)  HMMA
// ---------------------------------------------------------------------------

#define BATCH   4
#define SEQ     1024
#define DIM     1024
#define HEADS   16
#define HDIM    64
#define ROWS    (BATCH * SEQ)      // 4096
#define QKVDIM  (3 * DIM)          // 3072

__device__ __align__(256) float g_qkv[ROWS * QKVDIM];   // tf32-valued
__device__ __align__(256) float g_attn[ROWS * DIM];     // tf32-valued
__device__ __align__(256) float g_xr[ROWS * DIM];
__device__ __align__(256) float g_wr[QKVDIM * DIM];
__device__ __align__(256) float g_w1r[DIM * DIM];

// ===========================================================================
// helpers
// ===========================================================================
__device__ __forceinline__ uint32_t smem_u32(const void* p) {
    uint32_t a;
    asm("{ .reg .u64 t; cvta.to.shared.u64 t, %1; cvt.u32.u64 %0, t; }"
        : "=r"(a) : "l"(p));
    return a;
}
__device__ __forceinline__ uint32_t lds32(uint32_t addr) {
    uint32_t v;
    asm volatile("ld.shared.b32 %0, [%1];" : "=r"(v) : "r"(addr));
    return v;
}
__device__ __forceinline__ float ldsf(uint32_t addr) {
    float v;
    asm volatile("ld.shared.f32 %0, [%1];" : "=f"(v) : "r"(addr));
    return v;
}
__device__ __forceinline__ void cp16(uint32_t dst, const void* src) {
    asm volatile("cp.async.cg.shared.global [%0], [%1], 16;" :: "r"(dst), "l"(src));
}
#define CP_COMMIT() asm volatile("cp.async.commit_group;" ::: "memory")
#define CP_WAIT(n)  asm volatile("cp.async.wait_group %0;" :: "n"(n) : "memory")

__device__ __forceinline__ float rna_tf32(float x) {
    uint32_t u;
    asm("cvt.rna.tf32.f32 %0, %1;" : "=r"(u) : "f"(x));
    return __uint_as_float(u);
}

// m16n8k8 tf32 mma: D += A*B (row.col)
__device__ __forceinline__ void mma_16n8k8(
    float* c, const uint32_t* a, const uint32_t* b)
{
    asm volatile(
        "mma.sync.aligned.m16n8k8.row.col.f32.tf32.tf32.f32 "
        "{%0,%1,%2,%3}, {%4,%5,%6,%7}, {%8,%9}, {%0,%1,%2,%3};"
        : "+f"(c[0]), "+f"(c[1]), "+f"(c[2]), "+f"(c[3])
        : "r"(a[0]), "r"(a[1]), "r"(a[2]), "r"(a[3]), "r"(b[0]), "r"(b[1]));
}

// ===========================================================================
// tf32 rounding kernel
// ===========================================================================
__global__ __launch_bounds__(256) void round_tf32(
    const float* __restrict__ in, float* __restrict__ out, int n4)
{
    int i = blockIdx.x * blockDim.x + threadIdx.x;
    if (i >= n4) return;
    float4 v = ((const float4*)in)[i];
    float4 o;
    o.x = rna_tf32(v.x); o.y = rna_tf32(v.y);
    o.z = rna_tf32(v.z); o.w = rna_tf32(v.w);
    ((float4*)out)[i] = o;
}

// ===========================================================================
// mma.sync tf32 NT GEMM + bias:  C = A @ B^T + bias.
// 128x128 CTA tile, TK=32, 3-slot / 2-deep cp.async pipeline.
// __launch_bounds__(256, 2): regs capped at 128 so TWO CTAs are resident
// per SM (16 warps, two independent barrier domains) -> tensor pipe stays
// fed across K-tile boundaries. smem 110592 B x 2 = 216 KB <= 228 KB.
// ===========================================================================
#define TK        32
#define ROWB      144                  // 36 floats
#define ATILE_B   (128 * ROWB)
#define STAGE_B   (2 * ATILE_B)        // 36864
#define GSTAGES   3
#define GEMM_SMEM (GSTAGES * STAGE_B)  // 110592 B

template <bool ROUND_OUT>
__global__ __launch_bounds__(256, 2) void gemm_mma_tf32(
    const float* __restrict__ A, const float* __restrict__ B,
    const float* __restrict__ bias, float* __restrict__ C,
    int M, int N, int K)
{
    extern __shared__ char smem[];
    const uint32_t sb = smem_u32(smem);
    const int tid    = threadIdx.x;
    const int wid    = tid >> 5;
    const int lane   = tid & 31;
    const int g      = lane >> 2;
    const int tig    = lane & 3;
    const int warp_m = wid >> 1;
    const int warp_n = wid & 1;
    const int m0     = blockIdx.y * 128;
    const int n0     = blockIdx.x * 128;

    float c[2][8][4];
#pragma unroll
    for (int mt = 0; mt < 2; mt++)
#pragma unroll
        for (int nt = 0; nt < 8; nt++)
#pragma unroll
            for (int r = 0; r < 4; r++) c[mt][nt][r] = 0.0f;

    auto load_tile = [&](int slot, int k0) {
        const uint32_t aB = sb + slot * STAGE_B;
        const uint32_t bB = aB + ATILE_B;
#pragma unroll
        for (int i = 0; i < 4; i++) {
            const int idx = i * 256 + tid;
            const int row = idx >> 3;
            const int seg = idx & 7;
            cp16(aB + row * ROWB + seg * 16, A + (size_t)(m0 + row) * K + k0 + seg * 4);
            cp16(bB + row * ROWB + seg * 16, B + (size_t)(n0 + row) * K + k0 + seg * 4);
        }
        CP_COMMIT();
    };

    const int NT = K / TK;
    // prologue: 2 tiles in flight (slots 0,1 of 3)
    load_tile(0, 0);
    load_tile(1, TK);

    int slot = 0;
    for (int t = 0; t < NT; t++) {
        CP_WAIT(1);            // tile t ready; tile t+1 may pend
        __syncthreads();       // visibility + WAR guard for slot reuse
        if (t + 2 < NT) {
            int ns = slot + 2; if (ns >= GSTAGES) ns -= GSTAGES;
            load_tile(ns, (t + 2) * TK);
        }

        const uint32_t aB = sb + slot * STAGE_B;
        const uint32_t bB = aB + ATILE_B;

#pragma unroll
        for (int kk = 0; kk < TK; kk += 8) {
            uint32_t af[2][4];
            uint32_t bf[8][2];
#pragma unroll
            for (int mt = 0; mt < 2; mt++) {
                const int row = warp_m * 32 + mt * 16;
                af[mt][0] = lds32(aB + (row + g)     * ROWB + (kk + tig)     * 4);
                af[mt][1] = lds32(aB + (row + 8 + g) * ROWB + (kk + tig)     * 4);
                af[mt][2] = lds32(aB + (row + g)     * ROWB + (kk + tig + 4) * 4);
                af[mt][3] = lds32(aB + (row + 8 + g) * ROWB + (kk + tig + 4) * 4);
            }
#pragma unroll
            for (int nt = 0; nt < 8; nt++) {
                const int col = warp_n * 64 + nt * 8 + g;
                bf[nt][0] = lds32(bB + col * ROWB + (kk + tig)     * 4);
                bf[nt][1] = lds32(bB + col * ROWB + (kk + tig + 4) * 4);
            }
#pragma unroll
            for (int mt = 0; mt < 2; mt++)
#pragma unroll
                for (int nt = 0; nt < 8; nt++)
                    mma_16n8k8(c[mt][nt], af[mt], bf[nt]);
        }
        if (++slot >= GSTAGES) slot = 0;
    }

#pragma unroll
    for (int mt = 0; mt < 2; mt++) {
        const int row = m0 + warp_m * 32 + mt * 16 + g;
#pragma unroll
        for (int nt = 0; nt < 8; nt++) {
            const int col = n0 + warp_n * 64 + nt * 8 + tig * 2;
            const float bx = bias[col];
            const float by = bias[col + 1];
            float2 v0, v1;
            if (ROUND_OUT) {
                v0 = make_float2(rna_tf32(c[mt][nt][0] + bx), rna_tf32(c[mt][nt][1] + by));
                v1 = make_float2(rna_tf32(c[mt][nt][2] + bx), rna_tf32(c[mt][nt][3] + by));
            } else {
                v0 = make_float2(c[mt][nt][0] + bx, c[mt][nt][1] + by);
                v1 = make_float2(c[mt][nt][2] + bx, c[mt][nt][3] + by);
            }
            *(float2*)(C + (size_t)row * N + col)       = v0;
            *(float2*)(C + (size_t)(row + 8) * N + col) = v1;
        }
    }
}

// ===========================================================================
// Tensor-core flash attention (tf32 mma.sync), unchanged from R5 (passing).
// ===========================================================================
#define FA_QK_STRIDE 272
#define FA_QS_OFF    0
#define FA_QS_BUF    (64 * FA_QK_STRIDE)
#define FA_KS_OFF    FA_QS_BUF
#define FA_KS_BUF    (64 * FA_QK_STRIDE)
#define FA_VS_OFF    (FA_KS_OFF + 2 * FA_KS_BUF)
#define FA_VS_BUF    (64 * 256)
#define FA_SMEM      (FA_VS_OFF + 2 * FA_VS_BUF)   // 84992 B

__global__ __launch_bounds__(128) void flash_attn_tc(
    const float* __restrict__ qkv, float* __restrict__ out)
{
    extern __shared__ char smem[];
    const uint32_t sb = smem_u32(smem);
    const int tid  = threadIdx.x;
    const int wid  = tid >> 5;
    const int lane = tid & 31;
    const int g    = lane >> 2;
    const int tig  = lane & 3;
    const int q0   = blockIdx.x * 64;
    const int h    = blockIdx.y;
    const int b    = blockIdx.z;

    const float* qb = qkv + (size_t)b * SEQ * QKVDIM + (size_t)h * HDIM;
    const float* kb = qb + DIM;
    const float* vb = qb + 2 * DIM;

#pragma unroll
    for (int i = 0; i < 8; i++) {
        const int idx = i * 128 + tid;
        const int row = idx >> 4;
        const int seg = idx & 15;
        cp16(sb + FA_QS_OFF + row * FA_QK_STRIDE + seg * 16,
             qb + (size_t)(q0 + row) * QKVDIM + seg * 4);
    }
    CP_COMMIT();

    auto load_kv = [&](int slot, int jt) {
        const int j0 = jt * 64;
        const uint32_t kB = sb + FA_KS_OFF + slot * FA_KS_BUF;
        const uint32_t vB = sb + FA_VS_OFF + slot * FA_VS_BUF;
#pragma unroll
        for (int i = 0; i < 8; i++) {
            const int idx = i * 128 + tid;
            const int row = idx >> 4;
            const int seg = idx & 15;
            cp16(kB + row * FA_QK_STRIDE + seg * 16,
                 kb + (size_t)(j0 + row) * QKVDIM + seg * 4);
            cp16(vB + row * 256 + ((seg * 16) ^ ((row & 3) * 32)),
                 vb + (size_t)(j0 + row) * QKVDIM + seg * 4);
        }
        CP_COMMIT();
    };

    load_kv(0, 0);
    CP_WAIT(1);
    __syncthreads();

    uint32_t qf[8][4];
    {
        const uint32_t r0 = sb + FA_QS_OFF + (wid * 16 + g) * FA_QK_STRIDE;
        const uint32_t r8 = r0 + 8 * FA_QK_STRIDE;
#pragma unroll
        for (int ks = 0; ks < 8; ks++) {
            qf[ks][0] = __float_as_uint(ldsf(r0 + (ks * 8 + tig)     * 4) * 0.03125f);
            qf[ks][1] = __float_as_uint(ldsf(r8 + (ks * 8 + tig)     * 4) * 0.03125f);
            qf[ks][2] = __float_as_uint(ldsf(r0 + (ks * 8 + tig + 4) * 4) * 0.03125f);
            qf[ks][3] = __float_as_uint(ldsf(r8 + (ks * 8 + tig + 4) * 4) * 0.03125f);
        }
    }

    float o[8][4];
#pragma unroll
    for (int nt = 0; nt < 8; nt++)
#pragma unroll
        for (int r = 0; r < 4; r++) o[nt][r] = 0.0f;
    float m_r[2] = {-1e30f, -1e30f};
    float l_r[2] = {0.0f, 0.0f};

    const int s0  = tig >> 1;
    const int sel = tig & 1;
    const uint32_t vswz = tig * 32;

    for (int jt = 0; jt < SEQ / 64; jt++) {
        if (jt + 1 < SEQ / 64) {
            load_kv((jt + 1) & 1, jt + 1);
            CP_WAIT(1);
        } else {
            CP_WAIT(0);
        }
        __syncthreads();

        const uint32_t kB = sb + FA_KS_OFF + (jt & 1) * FA_KS_BUF;
        const uint32_t vB = sb + FA_VS_OFF + (jt & 1) * FA_VS_BUF;

        float c[8][4];
#pragma unroll
        for (int nt = 0; nt < 8; nt++)
#pragma unroll
            for (int r = 0; r < 4; r++) c[nt][r] = 0.0f;

#pragma unroll
        for (int ks = 0; ks < 8; ks++) {
            uint32_t bf[8][2];
#pragma unroll
            for (int nt = 0; nt < 8; nt++) {
                const uint32_t base =
                    kB + (nt * 8 + g) * FA_QK_STRIDE + (ks * 8 + tig) * 4;
                bf[nt][0] = lds32(base);
                bf[nt][1] = lds32(base + 16);
            }
#pragma unroll
            for (int nt = 0; nt < 8; nt++)
                mma_16n8k8(c[nt], qf[ks], bf[nt]);
        }

#pragma unroll
        for (int r = 0; r < 2; r++) {
            float mx = -1e30f;
#pragma unroll
            for (int nt = 0; nt < 8; nt++) {
                mx = fmaxf(mx, c[nt][2 * r]);
                mx = fmaxf(mx, c[nt][2 * r + 1]);
            }
            mx = fmaxf(mx, __shfl_xor_sync(0xffffffffu, mx, 1));
            mx = fmaxf(mx, __shfl_xor_sync(0xffffffffu, mx, 2));
            const float mnew  = fmaxf(m_r[r], mx);
            const float alpha = __expf(m_r[r] - mnew);
            float sum = 0.0f;
#pragma unroll
            for (int nt = 0; nt < 8; nt++) {
                const float p0 = __expf(c[nt][2 * r]     - mnew);
                const float p1 = __expf(c[nt][2 * r + 1] - mnew);
                c[nt][2 * r] = p0; c[nt][2 * r + 1] = p1;
                sum += p0 + p1;
            }
            sum += __shfl_xor_sync(0xffffffffu, sum, 1);
            sum += __shfl_xor_sync(0xffffffffu, sum, 2);
            l_r[r] = l_r[r] * alpha + sum;
            m_r[r] = mnew;
#pragma unroll
            for (int nt = 0; nt < 8; nt++) {
                o[nt][2 * r]     *= alpha;
                o[nt][2 * r + 1] *= alpha;
            }
        }

#pragma unroll
        for (int nt = 0; nt < 8; nt++)
#pragma unroll
            for (int r = 0; r < 4; r++) c[nt][r] = rna_tf32(c[nt][r]);

#pragma unroll
        for (int ks = 0; ks < 8; ks++) {
            const float x0  = __shfl_sync(0xffffffffu, c[ks][0], s0, 4);
            const float x1  = __shfl_sync(0xffffffffu, c[ks][1], s0, 4);
            const float y0  = __shfl_sync(0xffffffffu, c[ks][2], s0, 4);
            const float y1  = __shfl_sync(0xffffffffu, c[ks][3], s0, 4);
            const float x0b = __shfl_sync(0xffffffffu, c[ks][0], s0 + 2, 4);
            const float x1b = __shfl_sync(0xffffffffu, c[ks][1], s0 + 2, 4);
            const float y0b = __shfl_sync(0xffffffffu, c[ks][2], s0 + 2, 4);
            const float y1b = __shfl_sync(0xffffffffu, c[ks][3], s0 + 2, 4);
            uint32_t pa[4];
            pa[0] = __float_as_uint(sel ? x1  : x0);
            pa[1] = __float_as_uint(sel ? y1  : y0);
            pa[2] = __float_as_uint(sel ? x1b : x0b);
            pa[3] = __float_as_uint(sel ? y1b : y0b);

            uint32_t vf[8][2];
            const uint32_t vr0 = vB + (ks * 8 + tig) * 256;
            const uint32_t vr4 = vB + (ks * 8 + tig + 4) * 256;
#pragma unroll
            for (int nt = 0; nt < 8; nt++) {
                const uint32_t coff = ((nt * 8 + g) * 4) ^ vswz;
                vf[nt][0] = lds32(vr0 + coff);
                vf[nt][1] = lds32(vr4 + coff);
            }
#pragma unroll
            for (int nt = 0; nt < 8; nt++)
                mma_16n8k8(o[nt], pa, vf[nt]);
        }
        __syncthreads();
    }

    const float inv0 = 1.0f / l_r[0];
    const float inv1 = 1.0f / l_r[1];
    const size_t row0 = (size_t)b * SEQ + q0 + wid * 16 + g;
    const size_t row1 = row0 + 8;
#pragma unroll
    for (int nt = 0; nt < 8; nt++) {
        const int col = h * HDIM + nt * 8 + 2 * tig;
        float2 v0 = make_float2(rna_tf32(o[nt][0] * inv0), rna_tf32(o[nt][1] * inv0));
        float2 v1 = make_float2(rna_tf32(o[nt][2] * inv1), rna_tf32(o[nt][3] * inv1));
        *(float2*)(out + row0 * DIM + col) = v0;
        *(float2*)(out + row1 * DIM + col) = v1;
    }
}

// ===========================================================================
// Launch
// ===========================================================================
extern "C" void kernel_launch(void* const* d_in, const int* in_sizes, int n_in,
                              void* d_out, int out_size)
{
    const float* x    = (const float*)d_in[0];
    const float* Wqkv = (const float*)d_in[1];
    const float* bqkv = (const float*)d_in[2];
    const float* W1   = (const float*)d_in[3];
    const float* b1   = (const float*)d_in[4];
    float* out = (float*)d_out;

    float *qkv_p, *attn_p, *xr_p, *wr_p, *w1r_p;
    cudaGetSymbolAddress((void**)&qkv_p,  g_qkv);
    cudaGetSymbolAddress((void**)&attn_p, g_attn);
    cudaGetSymbolAddress((void**)&xr_p,   g_xr);
    cudaGetSymbolAddress((void**)&wr_p,   g_wr);
    cudaGetSymbolAddress((void**)&w1r_p,  g_w1r);

    cudaFuncSetAttribute(gemm_mma_tf32<true>,
                         cudaFuncAttributeMaxDynamicSharedMemorySize, GEMM_SMEM);
    cudaFuncSetAttribute(gemm_mma_tf32<false>,
                         cudaFuncAttributeMaxDynamicSharedMemorySize, GEMM_SMEM);
    cudaFuncSetAttribute(flash_attn_tc,
                         cudaFuncAttributeMaxDynamicSharedMemorySize, FA_SMEM);

    // 0) round GEMM operands to tf32 grid
    round_tf32<<<(ROWS * DIM / 4 + 255) / 256, 256>>>(x, xr_p, ROWS * DIM / 4);
    round_tf32<<<(QKVDIM * DIM / 4 + 255) / 256, 256>>>(Wqkv, wr_p, QKVDIM * DIM / 4);
    round_tf32<<<(DIM * DIM / 4 + 255) / 256, 256>>>(W1, w1r_p, DIM * DIM / 4);

    // 1) QKV projection (epilogue rounds -> attention inputs are tf32-exact)
    {
        dim3 grid(QKVDIM / 128, ROWS / 128);
        gemm_mma_tf32<true><<<grid, 256, GEMM_SMEM>>>(xr_p, wr_p, bqkv, qkv_p,
                                                      ROWS, QKVDIM, DIM);
    }

    // 2) Tensor-core flash attention
    {
        dim3 grid(SEQ / 64, HEADS, BATCH);
        flash_attn_tc<<<grid, 128, FA_SMEM>>>(qkv_p, attn_p);
    }

    // 3) Output projection (final output, unrounded)
    {
        dim3 grid(DIM / 128, ROWS / 128);
        gemm_mma_tf32<false><<<grid, 256, GEMM_SMEM>>>(attn_p, w1r_p, b1, out,
                                                       ROWS, DIM, DIM);
    }
}

// round 8
// speedup vs baseline: 3.9058x; 1.0025x over previous
#include <cuda_runtime.h>
#include <cuda_bf16.h>
#include <cstdint>

// ---------------------------------------------------------------------------
// Fused transformer block, fp32 in/out. All heavy math on mma.sync tf32.
//   qkv = x @ Wqkv^T + bqkv   (4096x3072x1024)  HMMA, epilogue tf32-rounds
//   attention: 16 heads, d=64, scale 1/32       HMMA flash attention
//   out = attn @ W1^T + b1    (4096x1024x1024)  HMMA
// ---------------------------------------------------------------------------

#define BATCH   4
#define SEQ     1024
#define DIM     1024
#define HEADS   16
#define HDIM    64
#define ROWS    (BATCH * SEQ)      // 4096
#define QKVDIM  (3 * DIM)          // 3072

__device__ __align__(256) float g_qkv[ROWS * QKVDIM];   // tf32-valued
__device__ __align__(256) float g_attn[ROWS * DIM];     // tf32-valued
__device__ __align__(256) float g_xr[ROWS * DIM];
__device__ __align__(256) float g_wr[QKVDIM * DIM];
__device__ __align__(256) float g_w1r[DIM * DIM];

// ===========================================================================
// helpers
// ===========================================================================
__device__ __forceinline__ uint32_t smem_u32(const void* p) {
    uint32_t a;
    asm("{ .reg .u64 t; cvta.to.shared.u64 t, %1; cvt.u32.u64 %0, t; }"
        : "=r"(a) : "l"(p));
    return a;
}
__device__ __forceinline__ uint32_t lds32(uint32_t addr) {
    uint32_t v;
    asm volatile("ld.shared.b32 %0, [%1];" : "=r"(v) : "r"(addr));
    return v;
}
__device__ __forceinline__ float ldsf(uint32_t addr) {
    float v;
    asm volatile("ld.shared.f32 %0, [%1];" : "=f"(v) : "r"(addr));
    return v;
}
__device__ __forceinline__ void cp16(uint32_t dst, const void* src) {
    asm volatile("cp.async.cg.shared.global [%0], [%1], 16;" :: "r"(dst), "l"(src));
}
#define CP_COMMIT() asm volatile("cp.async.commit_group;" ::: "memory")
#define CP_WAIT(n)  asm volatile("cp.async.wait_group %0;" :: "n"(n) : "memory")

__device__ __forceinline__ float rna_tf32(float x) {
    uint32_t u;
    asm("cvt.rna.tf32.f32 %0, %1;" : "=r"(u) : "f"(x));
    return __uint_as_float(u);
}

// m16n8k8 tf32 mma: D += A*B (row.col)
__device__ __forceinline__ void mma_16n8k8(
    float* c, const uint32_t* a, const uint32_t* b)
{
    asm volatile(
        "mma.sync.aligned.m16n8k8.row.col.f32.tf32.tf32.f32 "
        "{%0,%1,%2,%3}, {%4,%5,%6,%7}, {%8,%9}, {%0,%1,%2,%3};"
        : "+f"(c[0]), "+f"(c[1]), "+f"(c[2]), "+f"(c[3])
        : "r"(a[0]), "r"(a[1]), "r"(a[2]), "r"(a[3]), "r"(b[0]), "r"(b[1]));
}

// ===========================================================================
// tf32 rounding kernel
// ===========================================================================
__global__ __launch_bounds__(256) void round_tf32(
    const float* __restrict__ in, float* __restrict__ out, int n4)
{
    int i = blockIdx.x * blockDim.x + threadIdx.x;
    if (i >= n4) return;
    float4 v = ((const float4*)in)[i];
    float4 o;
    o.x = rna_tf32(v.x); o.y = rna_tf32(v.y);
    o.z = rna_tf32(v.z); o.w = rna_tf32(v.w);
    ((float4*)out)[i] = o;
}

// ===========================================================================
// mma.sync tf32 NT GEMM + bias:  C = A @ B^T + bias.
// CTA tile 128(m) x 256(n), TK=32, 2-stage cp.async double buffer, 256 thr.
// Warp grid 2(m) x 4(n); warp tile 64x64 -> smem bytes/MAC = 0.125 (was
// 0.1875 at 32x64), dropping crossbar demand below the 128 B/cyc/SM limit.
// 128 fp32 accumulators/thread -> single CTA/SM (by register count).
// ===========================================================================
#define TK        32
#define ROWB      144                        // 36 floats
#define ATILE_B   (128 * ROWB)               // 18432
#define BTILE_B   (256 * ROWB)               // 36864
#define STAGE_B   (ATILE_B + BTILE_B)        // 55296
#define GEMM_SMEM (2 * STAGE_B)              // 110592 B

template <bool ROUND_OUT>
__global__ __launch_bounds__(256) void gemm_mma_tf32(
    const float* __restrict__ A, const float* __restrict__ B,
    const float* __restrict__ bias, float* __restrict__ C,
    int M, int N, int K)
{
    extern __shared__ char smem[];
    const uint32_t sb = smem_u32(smem);
    const int tid    = threadIdx.x;
    const int wid    = tid >> 5;
    const int lane   = tid & 31;
    const int g      = lane >> 2;
    const int tig    = lane & 3;
    const int warp_m = wid & 1;        // 0..1  (64 rows each)
    const int warp_n = wid >> 1;       // 0..3  (64 cols each)
    const int m0     = blockIdx.y * 128;
    const int n0     = blockIdx.x * 256;

    float c[4][8][4];
#pragma unroll
    for (int mt = 0; mt < 4; mt++)
#pragma unroll
        for (int nt = 0; nt < 8; nt++)
#pragma unroll
            for (int r = 0; r < 4; r++) c[mt][nt][r] = 0.0f;

    auto load_tile = [&](int slot, int k0) {
        const uint32_t aB = sb + slot * STAGE_B;
        const uint32_t bB = aB + ATILE_B;
        // A: 128 rows x 8 segs = 1024 -> 4 per thread
#pragma unroll
        for (int i = 0; i < 4; i++) {
            const int idx = i * 256 + tid;
            const int row = idx >> 3;
            const int seg = idx & 7;
            cp16(aB + row * ROWB + seg * 16, A + (size_t)(m0 + row) * K + k0 + seg * 4);
        }
        // B: 256 rows x 8 segs = 2048 -> 8 per thread
#pragma unroll
        for (int i = 0; i < 8; i++) {
            const int idx = i * 256 + tid;
            const int row = idx >> 3;
            const int seg = idx & 7;
            cp16(bB + row * ROWB + seg * 16, B + (size_t)(n0 + row) * K + k0 + seg * 4);
        }
        CP_COMMIT();
    };

    const int NT = K / TK;
    load_tile(0, 0);

    for (int t = 0; t < NT; t++) {
        if (t + 1 < NT) {
            load_tile((t + 1) & 1, (t + 1) * TK);
            CP_WAIT(1);
        } else {
            CP_WAIT(0);
        }
        __syncthreads();

        const uint32_t aB = sb + (t & 1) * STAGE_B;
        const uint32_t bB = aB + ATILE_B;

#pragma unroll
        for (int kk = 0; kk < TK; kk += 8) {
            uint32_t af[4][4];
            uint32_t bf[8][2];
#pragma unroll
            for (int mt = 0; mt < 4; mt++) {
                const int row = warp_m * 64 + mt * 16;
                af[mt][0] = lds32(aB + (row + g)     * ROWB + (kk + tig)     * 4);
                af[mt][1] = lds32(aB + (row + 8 + g) * ROWB + (kk + tig)     * 4);
                af[mt][2] = lds32(aB + (row + g)     * ROWB + (kk + tig + 4) * 4);
                af[mt][3] = lds32(aB + (row + 8 + g) * ROWB + (kk + tig + 4) * 4);
            }
#pragma unroll
            for (int nt = 0; nt < 8; nt++) {
                const int col = warp_n * 64 + nt * 8 + g;
                bf[nt][0] = lds32(bB + col * ROWB + (kk + tig)     * 4);
                bf[nt][1] = lds32(bB + col * ROWB + (kk + tig + 4) * 4);
            }
#pragma unroll
            for (int mt = 0; mt < 4; mt++)
#pragma unroll
                for (int nt = 0; nt < 8; nt++)
                    mma_16n8k8(c[mt][nt], af[mt], bf[nt]);
        }
        __syncthreads();
    }

#pragma unroll
    for (int mt = 0; mt < 4; mt++) {
        const int row = m0 + warp_m * 64 + mt * 16 + g;
#pragma unroll
        for (int nt = 0; nt < 8; nt++) {
            const int col = n0 + warp_n * 64 + nt * 8 + tig * 2;
            const float bx = bias[col];
            const float by = bias[col + 1];
            float2 v0, v1;
            if (ROUND_OUT) {
                v0 = make_float2(rna_tf32(c[mt][nt][0] + bx), rna_tf32(c[mt][nt][1] + by));
                v1 = make_float2(rna_tf32(c[mt][nt][2] + bx), rna_tf32(c[mt][nt][3] + by));
            } else {
                v0 = make_float2(c[mt][nt][0] + bx, c[mt][nt][1] + by);
                v1 = make_float2(c[mt][nt][2] + bx, c[mt][nt][3] + by);
            }
            *(float2*)(C + (size_t)row * N + col)       = v0;
            *(float2*)(C + (size_t)(row + 8) * N + col) = v1;
        }
    }
}

// ===========================================================================
// Tensor-core flash attention (tf32 mma.sync), unchanged from R5 (passing).
// ===========================================================================
#define FA_QK_STRIDE 272
#define FA_QS_OFF    0
#define FA_QS_BUF    (64 * FA_QK_STRIDE)
#define FA_KS_OFF    FA_QS_BUF
#define FA_KS_BUF    (64 * FA_QK_STRIDE)
#define FA_VS_OFF    (FA_KS_OFF + 2 * FA_KS_BUF)
#define FA_VS_BUF    (64 * 256)
#define FA_SMEM      (FA_VS_OFF + 2 * FA_VS_BUF)   // 84992 B

__global__ __launch_bounds__(128) void flash_attn_tc(
    const float* __restrict__ qkv, float* __restrict__ out)
{
    extern __shared__ char smem[];
    const uint32_t sb = smem_u32(smem);
    const int tid  = threadIdx.x;
    const int wid  = tid >> 5;
    const int lane = tid & 31;
    const int g    = lane >> 2;
    const int tig  = lane & 3;
    const int q0   = blockIdx.x * 64;
    const int h    = blockIdx.y;
    const int b    = blockIdx.z;

    const float* qb = qkv + (size_t)b * SEQ * QKVDIM + (size_t)h * HDIM;
    const float* kb = qb + DIM;
    const float* vb = qb + 2 * DIM;

#pragma unroll
    for (int i = 0; i < 8; i++) {
        const int idx = i * 128 + tid;
        const int row = idx >> 4;
        const int seg = idx & 15;
        cp16(sb + FA_QS_OFF + row * FA_QK_STRIDE + seg * 16,
             qb + (size_t)(q0 + row) * QKVDIM + seg * 4);
    }
    CP_COMMIT();

    auto load_kv = [&](int slot, int jt) {
        const int j0 = jt * 64;
        const uint32_t kB = sb + FA_KS_OFF + slot * FA_KS_BUF;
        const uint32_t vB = sb + FA_VS_OFF + slot * FA_VS_BUF;
#pragma unroll
        for (int i = 0; i < 8; i++) {
            const int idx = i * 128 + tid;
            const int row = idx >> 4;
            const int seg = idx & 15;
            cp16(kB + row * FA_QK_STRIDE + seg * 16,
                 kb + (size_t)(j0 + row) * QKVDIM + seg * 4);
            cp16(vB + row * 256 + ((seg * 16) ^ ((row & 3) * 32)),
                 vb + (size_t)(j0 + row) * QKVDIM + seg * 4);
        }
        CP_COMMIT();
    };

    load_kv(0, 0);
    CP_WAIT(1);
    __syncthreads();

    uint32_t qf[8][4];
    {
        const uint32_t r0 = sb + FA_QS_OFF + (wid * 16 + g) * FA_QK_STRIDE;
        const uint32_t r8 = r0 + 8 * FA_QK_STRIDE;
#pragma unroll
        for (int ks = 0; ks < 8; ks++) {
            qf[ks][0] = __float_as_uint(ldsf(r0 + (ks * 8 + tig)     * 4) * 0.03125f);
            qf[ks][1] = __float_as_uint(ldsf(r8 + (ks * 8 + tig)     * 4) * 0.03125f);
            qf[ks][2] = __float_as_uint(ldsf(r0 + (ks * 8 + tig + 4) * 4) * 0.03125f);
            qf[ks][3] = __float_as_uint(ldsf(r8 + (ks * 8 + tig + 4) * 4) * 0.03125f);
        }
    }

    float o[8][4];
#pragma unroll
    for (int nt = 0; nt < 8; nt++)
#pragma unroll
        for (int r = 0; r < 4; r++) o[nt][r] = 0.0f;
    float m_r[2] = {-1e30f, -1e30f};
    float l_r[2] = {0.0f, 0.0f};

    const int s0  = tig >> 1;
    const int sel = tig & 1;
    const uint32_t vswz = tig * 32;

    for (int jt = 0; jt < SEQ / 64; jt++) {
        if (jt + 1 < SEQ / 64) {
            load_kv((jt + 1) & 1, jt + 1);
            CP_WAIT(1);
        } else {
            CP_WAIT(0);
        }
        __syncthreads();

        const uint32_t kB = sb + FA_KS_OFF + (jt & 1) * FA_KS_BUF;
        const uint32_t vB = sb + FA_VS_OFF + (jt & 1) * FA_VS_BUF;

        float c[8][4];
#pragma unroll
        for (int nt = 0; nt < 8; nt++)
#pragma unroll
            for (int r = 0; r < 4; r++) c[nt][r] = 0.0f;

#pragma unroll
        for (int ks = 0; ks < 8; ks++) {
            uint32_t bf[8][2];
#pragma unroll
            for (int nt = 0; nt < 8; nt++) {
                const uint32_t base =
                    kB + (nt * 8 + g) * FA_QK_STRIDE + (ks * 8 + tig) * 4;
                bf[nt][0] = lds32(base);
                bf[nt][1] = lds32(base + 16);
            }
#pragma unroll
            for (int nt = 0; nt < 8; nt++)
                mma_16n8k8(c[nt], qf[ks], bf[nt]);
        }

#pragma unroll
        for (int r = 0; r < 2; r++) {
            float mx = -1e30f;
#pragma unroll
            for (int nt = 0; nt < 8; nt++) {
                mx = fmaxf(mx, c[nt][2 * r]);
                mx = fmaxf(mx, c[nt][2 * r + 1]);
            }
            mx = fmaxf(mx, __shfl_xor_sync(0xffffffffu, mx, 1));
            mx = fmaxf(mx, __shfl_xor_sync(0xffffffffu, mx, 2));
            const float mnew  = fmaxf(m_r[r], mx);
            const float alpha = __expf(m_r[r] - mnew);
            float sum = 0.0f;
#pragma unroll
            for (int nt = 0; nt < 8; nt++) {
                const float p0 = __expf(c[nt][2 * r]     - mnew);
                const float p1 = __expf(c[nt][2 * r + 1] - mnew);
                c[nt][2 * r] = p0; c[nt][2 * r + 1] = p1;
                sum += p0 + p1;
            }
            sum += __shfl_xor_sync(0xffffffffu, sum, 1);
            sum += __shfl_xor_sync(0xffffffffu, sum, 2);
            l_r[r] = l_r[r] * alpha + sum;
            m_r[r] = mnew;
#pragma unroll
            for (int nt = 0; nt < 8; nt++) {
                o[nt][2 * r]     *= alpha;
                o[nt][2 * r + 1] *= alpha;
            }
        }

#pragma unroll
        for (int nt = 0; nt < 8; nt++)
#pragma unroll
            for (int r = 0; r < 4; r++) c[nt][r] = rna_tf32(c[nt][r]);

#pragma unroll
        for (int ks = 0; ks < 8; ks++) {
            const float x0  = __shfl_sync(0xffffffffu, c[ks][0], s0, 4);
            const float x1  = __shfl_sync(0xffffffffu, c[ks][1], s0, 4);
            const float y0  = __shfl_sync(0xffffffffu, c[ks][2], s0, 4);
            const float y1  = __shfl_sync(0xffffffffu, c[ks][3], s0, 4);
            const float x0b = __shfl_sync(0xffffffffu, c[ks][0], s0 + 2, 4);
            const float x1b = __shfl_sync(0xffffffffu, c[ks][1], s0 + 2, 4);
            const float y0b = __shfl_sync(0xffffffffu, c[ks][2], s0 + 2, 4);
            const float y1b = __shfl_sync(0xffffffffu, c[ks][3], s0 + 2, 4);
            uint32_t pa[4];
            pa[0] = __float_as_uint(sel ? x1  : x0);
            pa[1] = __float_as_uint(sel ? y1  : y0);
            pa[2] = __float_as_uint(sel ? x1b : x0b);
            pa[3] = __float_as_uint(sel ? y1b : y0b);

            uint32_t vf[8][2];
            const uint32_t vr0 = vB + (ks * 8 + tig) * 256;
            const uint32_t vr4 = vB + (ks * 8 + tig + 4) * 256;
#pragma unroll
            for (int nt = 0; nt < 8; nt++) {
                const uint32_t coff = ((nt * 8 + g) * 4) ^ vswz;
                vf[nt][0] = lds32(vr0 + coff);
                vf[nt][1] = lds32(vr4 + coff);
            }
#pragma unroll
            for (int nt = 0; nt < 8; nt++)
                mma_16n8k8(o[nt], pa, vf[nt]);
        }
        __syncthreads();
    }

    const float inv0 = 1.0f / l_r[0];
    const float inv1 = 1.0f / l_r[1];
    const size_t row0 = (size_t)b * SEQ + q0 + wid * 16 + g;
    const size_t row1 = row0 + 8;
#pragma unroll
    for (int nt = 0; nt < 8; nt++) {
        const int col = h * HDIM + nt * 8 + 2 * tig;
        float2 v0 = make_float2(rna_tf32(o[nt][0] * inv0), rna_tf32(o[nt][1] * inv0));
        float2 v1 = make_float2(rna_tf32(o[nt][2] * inv1), rna_tf32(o[nt][3] * inv1));
        *(float2*)(out + row0 * DIM + col) = v0;
        *(float2*)(out + row1 * DIM + col) = v1;
    }
}

// ===========================================================================
// Launch
// ===========================================================================
extern "C" void kernel_launch(void* const* d_in, const int* in_sizes, int n_in,
                              void* d_out, int out_size)
{
    const float* x    = (const float*)d_in[0];
    const float* Wqkv = (const float*)d_in[1];
    const float* bqkv = (const float*)d_in[2];
    const float* W1   = (const float*)d_in[3];
    const float* b1   = (const float*)d_in[4];
    float* out = (float*)d_out;

    float *qkv_p, *attn_p, *xr_p, *wr_p, *w1r_p;
    cudaGetSymbolAddress((void**)&qkv_p,  g_qkv);
    cudaGetSymbolAddress((void**)&attn_p, g_attn);
    cudaGetSymbolAddress((void**)&xr_p,   g_xr);
    cudaGetSymbolAddress((void**)&wr_p,   g_wr);
    cudaGetSymbolAddress((void**)&w1r_p,  g_w1r);

    cudaFuncSetAttribute(gemm_mma_tf32<true>,
                         cudaFuncAttributeMaxDynamicSharedMemorySize, GEMM_SMEM);
    cudaFuncSetAttribute(gemm_mma_tf32<false>,
                         cudaFuncAttributeMaxDynamicSharedMemorySize, GEMM_SMEM);
    cudaFuncSetAttribute(flash_attn_tc,
                         cudaFuncAttributeMaxDynamicSharedMemorySize, FA_SMEM);

    // 0) round GEMM operands to tf32 grid
    round_tf32<<<(ROWS * DIM / 4 + 255) / 256, 256>>>(x, xr_p, ROWS * DIM / 4);
    round_tf32<<<(QKVDIM * DIM / 4 + 255) / 256, 256>>>(Wqkv, wr_p, QKVDIM * DIM / 4);
    round_tf32<<<(DIM * DIM / 4 + 255) / 256, 256>>>(W1, w1r_p, DIM * DIM / 4);

    // 1) QKV projection (epilogue rounds -> attention inputs are tf32-exact)
    {
        dim3 grid(QKVDIM / 256, ROWS / 128);
        gemm_mma_tf32<true><<<grid, 256, GEMM_SMEM>>>(xr_p, wr_p, bqkv, qkv_p,
                                                      ROWS, QKVDIM, DIM);
    }

    // 2) Tensor-core flash attention
    {
        dim3 grid(SEQ / 64, HEADS, BATCH);
        flash_attn_tc<<<grid, 128, FA_SMEM>>>(qkv_p, attn_p);
    }

    // 3) Output projection (final output, unrounded)
    {
        dim3 grid(DIM / 256, ROWS / 128);
        gemm_mma_tf32<false><<<grid, 256, GEMM_SMEM>>>(attn_p, w1r_p, b1, out,
                                                       ROWS, DIM, DIM);
    }
}

// round 9
// speedup vs baseline: 5.4051x; 1.3839x over previous
#include <cuda_runtime.h>
#include <cuda_bf16.h>
#include <cuda_fp16.h>
#include <cstdint>

// ---------------------------------------------------------------------------
// Fused transformer block, fp32 in/out.
//   qkv = x @ Wqkv^T + bqkv   (4096x3072x1024)  fp16 HMMA m16n8k16
//   attention: 16 heads, d=64, scale 1/32       tf32 HMMA flash attention
//   out = attn @ W1^T + b1    (4096x1024x1024)  fp16 HMMA m16n8k16
// fp16 has the same 10-bit mantissa as tf32 -> same rounding error, but
// mma.sync m16n8k16 does 2x the math per instruction vs tf32 m16n8k8.
// ---------------------------------------------------------------------------

#define BATCH   4
#define SEQ     1024
#define DIM     1024
#define HEADS   16
#define HDIM    64
#define ROWS    (BATCH * SEQ)      // 4096
#define QKVDIM  (3 * DIM)          // 3072

__device__ __align__(256) float  g_qkv[ROWS * QKVDIM];    // tf32-valued fp32
__device__ __align__(256) __half g_attn_h[ROWS * DIM];    // attention out, fp16
__device__ __align__(256) __half g_xh[ROWS * DIM];
__device__ __align__(256) __half g_wh[QKVDIM * DIM];
__device__ __align__(256) __half g_w1h[DIM * DIM];

// ===========================================================================
// helpers
// ===========================================================================
__device__ __forceinline__ uint32_t smem_u32(const void* p) {
    uint32_t a;
    asm("{ .reg .u64 t; cvta.to.shared.u64 t, %1; cvt.u32.u64 %0, t; }"
        : "=r"(a) : "l"(p));
    return a;
}
__device__ __forceinline__ uint32_t lds32(uint32_t addr) {
    uint32_t v;
    asm volatile("ld.shared.b32 %0, [%1];" : "=r"(v) : "r"(addr));
    return v;
}
__device__ __forceinline__ float ldsf(uint32_t addr) {
    float v;
    asm volatile("ld.shared.f32 %0, [%1];" : "=f"(v) : "r"(addr));
    return v;
}
__device__ __forceinline__ void cp16(uint32_t dst, const void* src) {
    asm volatile("cp.async.cg.shared.global [%0], [%1], 16;" :: "r"(dst), "l"(src));
}
#define CP_COMMIT() asm volatile("cp.async.commit_group;" ::: "memory")
#define CP_WAIT(n)  asm volatile("cp.async.wait_group %0;" :: "n"(n) : "memory")

__device__ __forceinline__ float rna_tf32(float x) {
    uint32_t u;
    asm("cvt.rna.tf32.f32 %0, %1;" : "=r"(u) : "f"(x));
    return __uint_as_float(u);
}

// tf32 m16n8k8 (attention)
__device__ __forceinline__ void mma_16n8k8(
    float* c, const uint32_t* a, const uint32_t* b)
{
    asm volatile(
        "mma.sync.aligned.m16n8k8.row.col.f32.tf32.tf32.f32 "
        "{%0,%1,%2,%3}, {%4,%5,%6,%7}, {%8,%9}, {%0,%1,%2,%3};"
        : "+f"(c[0]), "+f"(c[1]), "+f"(c[2]), "+f"(c[3])
        : "r"(a[0]), "r"(a[1]), "r"(a[2]), "r"(a[3]), "r"(b[0]), "r"(b[1]));
}

// fp16 m16n8k16, fp32 accumulate (GEMMs)
__device__ __forceinline__ void mma_16n8k16_f16(
    float* c, const uint32_t* a, const uint32_t* b)
{
    asm volatile(
        "mma.sync.aligned.m16n8k16.row.col.f32.f16.f16.f32 "
        "{%0,%1,%2,%3}, {%4,%5,%6,%7}, {%8,%9}, {%0,%1,%2,%3};"
        : "+f"(c[0]), "+f"(c[1]), "+f"(c[2]), "+f"(c[3])
        : "r"(a[0]), "r"(a[1]), "r"(a[2]), "r"(a[3]), "r"(b[0]), "r"(b[1]));
}

// ===========================================================================
// fp32 -> fp16 conversion kernel (2 floats / thread)
// ===========================================================================
__global__ __launch_bounds__(256) void to_half(
    const float* __restrict__ in, __half* __restrict__ out, int n2)
{
    int i = blockIdx.x * blockDim.x + threadIdx.x;
    if (i >= n2) return;
    float2 v = ((const float2*)in)[i];
    ((__half2*)out)[i] = __floats2half2_rn(v.x, v.y);
}

// ===========================================================================
// fp16 NT GEMM + bias:  C[M,N] = A[M,K] @ B[N,K]^T + bias[N]   (fp32 accum)
// CTA tile 128(m) x 256(n), K-tile 64, 2-stage cp.async, 256 thr.
// Warp grid 2(m) x 4(n), warp tile 64x64, m16n8k16.
// smem rows: 64 halfs (128 B) at stride 144 B -> frag banks (4g+tig)+const,
// conflict-free; 16B-aligned for cp.async.
// ===========================================================================
#define HTK       64
#define HROWB     144
#define HATILE    (128 * HROWB)              // 18432
#define HBTILE    (256 * HROWB)              // 36864
#define HSTAGE    (HATILE + HBTILE)          // 55296
#define HGEMM_SMEM (2 * HSTAGE)              // 110592 B

template <bool ROUND_OUT>
__global__ __launch_bounds__(256) void gemm_mma_f16(
    const __half* __restrict__ A, const __half* __restrict__ B,
    const float* __restrict__ bias, float* __restrict__ C,
    int M, int N, int K)
{
    extern __shared__ char smem[];
    const uint32_t sb = smem_u32(smem);
    const int tid    = threadIdx.x;
    const int wid    = tid >> 5;
    const int lane   = tid & 31;
    const int g      = lane >> 2;
    const int tig    = lane & 3;
    const int warp_m = wid & 1;        // 0..1  (64 rows)
    const int warp_n = wid >> 1;       // 0..3  (64 cols)
    const int m0     = blockIdx.y * 128;
    const int n0     = blockIdx.x * 256;

    float c[4][8][4];
#pragma unroll
    for (int mt = 0; mt < 4; mt++)
#pragma unroll
        for (int nt = 0; nt < 8; nt++)
#pragma unroll
            for (int r = 0; r < 4; r++) c[mt][nt][r] = 0.0f;

    auto load_tile = [&](int slot, int k0) {
        const uint32_t aB = sb + slot * HSTAGE;
        const uint32_t bB = aB + HATILE;
        // A: 128 rows x 8 segs (16B = 8 halfs) = 1024 -> 4 / thread
#pragma unroll
        for (int i = 0; i < 4; i++) {
            const int idx = i * 256 + tid;
            const int row = idx >> 3;
            const int seg = idx & 7;
            cp16(aB + row * HROWB + seg * 16, A + (size_t)(m0 + row) * K + k0 + seg * 8);
        }
        // B: 256 rows x 8 segs = 2048 -> 8 / thread
#pragma unroll
        for (int i = 0; i < 8; i++) {
            const int idx = i * 256 + tid;
            const int row = idx >> 3;
            const int seg = idx & 7;
            cp16(bB + row * HROWB + seg * 16, B + (size_t)(n0 + row) * K + k0 + seg * 8);
        }
        CP_COMMIT();
    };

    const int NT = K / HTK;
    load_tile(0, 0);

    for (int t = 0; t < NT; t++) {
        if (t + 1 < NT) {
            load_tile((t + 1) & 1, (t + 1) * HTK);
            CP_WAIT(1);
        } else {
            CP_WAIT(0);
        }
        __syncthreads();

        const uint32_t aB = sb + (t & 1) * HSTAGE;
        const uint32_t bB = aB + HATILE;

#pragma unroll
        for (int kk = 0; kk < HTK; kk += 16) {
            uint32_t af[4][4];
            uint32_t bf[8][2];
#pragma unroll
            for (int mt = 0; mt < 4; mt++) {
                const int row = warp_m * 64 + mt * 16;
                const uint32_t base = aB + (row + g) * HROWB + (kk + 2 * tig) * 2;
                af[mt][0] = lds32(base);                  // row g,   k 2tig..+1
                af[mt][1] = lds32(base + 8 * HROWB);      // row g+8
                af[mt][2] = lds32(base + 16);             // row g,   k +8
                af[mt][3] = lds32(base + 8 * HROWB + 16); // row g+8, k +8
            }
#pragma unroll
            for (int nt = 0; nt < 8; nt++) {
                const int col = warp_n * 64 + nt * 8 + g;
                const uint32_t base = bB + col * HROWB + (kk + 2 * tig) * 2;
                bf[nt][0] = lds32(base);
                bf[nt][1] = lds32(base + 16);
            }
#pragma unroll
            for (int mt = 0; mt < 4; mt++)
#pragma unroll
                for (int nt = 0; nt < 8; nt++)
                    mma_16n8k16_f16(c[mt][nt], af[mt], bf[nt]);
        }
        __syncthreads();
    }

#pragma unroll
    for (int mt = 0; mt < 4; mt++) {
        const int row = m0 + warp_m * 64 + mt * 16 + g;
#pragma unroll
        for (int nt = 0; nt < 8; nt++) {
            const int col = n0 + warp_n * 64 + nt * 8 + tig * 2;
            const float bx = bias[col];
            const float by = bias[col + 1];
            float2 v0, v1;
            if (ROUND_OUT) {   // feed attention: make values tf32-exact
                v0 = make_float2(rna_tf32(c[mt][nt][0] + bx), rna_tf32(c[mt][nt][1] + by));
                v1 = make_float2(rna_tf32(c[mt][nt][2] + bx), rna_tf32(c[mt][nt][3] + by));
            } else {
                v0 = make_float2(c[mt][nt][0] + bx, c[mt][nt][1] + by);
                v1 = make_float2(c[mt][nt][2] + bx, c[mt][nt][3] + by);
            }
            *(float2*)(C + (size_t)row * N + col)       = v0;
            *(float2*)(C + (size_t)(row + 8) * N + col) = v1;
        }
    }
}

// ===========================================================================
// Tensor-core flash attention (tf32 mma.sync) — math unchanged from R5;
// epilogue now writes fp16 (feeds the fp16 proj GEMM).
// ===========================================================================
#define FA_QK_STRIDE 272
#define FA_QS_OFF    0
#define FA_QS_BUF    (64 * FA_QK_STRIDE)
#define FA_KS_OFF    FA_QS_BUF
#define FA_KS_BUF    (64 * FA_QK_STRIDE)
#define FA_VS_OFF    (FA_KS_OFF + 2 * FA_KS_BUF)
#define FA_VS_BUF    (64 * 256)
#define FA_SMEM      (FA_VS_OFF + 2 * FA_VS_BUF)   // 84992 B

__global__ __launch_bounds__(128) void flash_attn_tc(
    const float* __restrict__ qkv, __half* __restrict__ out)
{
    extern __shared__ char smem[];
    const uint32_t sb = smem_u32(smem);
    const int tid  = threadIdx.x;
    const int wid  = tid >> 5;
    const int lane = tid & 31;
    const int g    = lane >> 2;
    const int tig  = lane & 3;
    const int q0   = blockIdx.x * 64;
    const int h    = blockIdx.y;
    const int b    = blockIdx.z;

    const float* qb = qkv + (size_t)b * SEQ * QKVDIM + (size_t)h * HDIM;
    const float* kb = qb + DIM;
    const float* vb = qb + 2 * DIM;

#pragma unroll
    for (int i = 0; i < 8; i++) {
        const int idx = i * 128 + tid;
        const int row = idx >> 4;
        const int seg = idx & 15;
        cp16(sb + FA_QS_OFF + row * FA_QK_STRIDE + seg * 16,
             qb + (size_t)(q0 + row) * QKVDIM + seg * 4);
    }
    CP_COMMIT();

    auto load_kv = [&](int slot, int jt) {
        const int j0 = jt * 64;
        const uint32_t kB = sb + FA_KS_OFF + slot * FA_KS_BUF;
        const uint32_t vB = sb + FA_VS_OFF + slot * FA_VS_BUF;
#pragma unroll
        for (int i = 0; i < 8; i++) {
            const int idx = i * 128 + tid;
            const int row = idx >> 4;
            const int seg = idx & 15;
            cp16(kB + row * FA_QK_STRIDE + seg * 16,
                 kb + (size_t)(j0 + row) * QKVDIM + seg * 4);
            cp16(vB + row * 256 + ((seg * 16) ^ ((row & 3) * 32)),
                 vb + (size_t)(j0 + row) * QKVDIM + seg * 4);
        }
        CP_COMMIT();
    };

    load_kv(0, 0);
    CP_WAIT(1);
    __syncthreads();

    uint32_t qf[8][4];
    {
        const uint32_t r0 = sb + FA_QS_OFF + (wid * 16 + g) * FA_QK_STRIDE;
        const uint32_t r8 = r0 + 8 * FA_QK_STRIDE;
#pragma unroll
        for (int ks = 0; ks < 8; ks++) {
            qf[ks][0] = __float_as_uint(ldsf(r0 + (ks * 8 + tig)     * 4) * 0.03125f);
            qf[ks][1] = __float_as_uint(ldsf(r8 + (ks * 8 + tig)     * 4) * 0.03125f);
            qf[ks][2] = __float_as_uint(ldsf(r0 + (ks * 8 + tig + 4) * 4) * 0.03125f);
            qf[ks][3] = __float_as_uint(ldsf(r8 + (ks * 8 + tig + 4) * 4) * 0.03125f);
        }
    }

    float o[8][4];
#pragma unroll
    for (int nt = 0; nt < 8; nt++)
#pragma unroll
        for (int r = 0; r < 4; r++) o[nt][r] = 0.0f;
    float m_r[2] = {-1e30f, -1e30f};
    float l_r[2] = {0.0f, 0.0f};

    const int s0  = tig >> 1;
    const int sel = tig & 1;
    const uint32_t vswz = tig * 32;

    for (int jt = 0; jt < SEQ / 64; jt++) {
        if (jt + 1 < SEQ / 64) {
            load_kv((jt + 1) & 1, jt + 1);
            CP_WAIT(1);
        } else {
            CP_WAIT(0);
        }
        __syncthreads();

        const uint32_t kB = sb + FA_KS_OFF + (jt & 1) * FA_KS_BUF;
        const uint32_t vB = sb + FA_VS_OFF + (jt & 1) * FA_VS_BUF;

        float c[8][4];
#pragma unroll
        for (int nt = 0; nt < 8; nt++)
#pragma unroll
            for (int r = 0; r < 4; r++) c[nt][r] = 0.0f;

#pragma unroll
        for (int ks = 0; ks < 8; ks++) {
            uint32_t bf[8][2];
#pragma unroll
            for (int nt = 0; nt < 8; nt++) {
                const uint32_t base =
                    kB + (nt * 8 + g) * FA_QK_STRIDE + (ks * 8 + tig) * 4;
                bf[nt][0] = lds32(base);
                bf[nt][1] = lds32(base + 16);
            }
#pragma unroll
            for (int nt = 0; nt < 8; nt++)
                mma_16n8k8(c[nt], qf[ks], bf[nt]);
        }

#pragma unroll
        for (int r = 0; r < 2; r++) {
            float mx = -1e30f;
#pragma unroll
            for (int nt = 0; nt < 8; nt++) {
                mx = fmaxf(mx, c[nt][2 * r]);
                mx = fmaxf(mx, c[nt][2 * r + 1]);
            }
            mx = fmaxf(mx, __shfl_xor_sync(0xffffffffu, mx, 1));
            mx = fmaxf(mx, __shfl_xor_sync(0xffffffffu, mx, 2));
            const float mnew  = fmaxf(m_r[r], mx);
            const float alpha = __expf(m_r[r] - mnew);
            float sum = 0.0f;
#pragma unroll
            for (int nt = 0; nt < 8; nt++) {
                const float p0 = __expf(c[nt][2 * r]     - mnew);
                const float p1 = __expf(c[nt][2 * r + 1] - mnew);
                c[nt][2 * r] = p0; c[nt][2 * r + 1] = p1;
                sum += p0 + p1;
            }
            sum += __shfl_xor_sync(0xffffffffu, sum, 1);
            sum += __shfl_xor_sync(0xffffffffu, sum, 2);
            l_r[r] = l_r[r] * alpha + sum;
            m_r[r] = mnew;
#pragma unroll
            for (int nt = 0; nt < 8; nt++) {
                o[nt][2 * r]     *= alpha;
                o[nt][2 * r + 1] *= alpha;
            }
        }

#pragma unroll
        for (int nt = 0; nt < 8; nt++)
#pragma unroll
            for (int r = 0; r < 4; r++) c[nt][r] = rna_tf32(c[nt][r]);

#pragma unroll
        for (int ks = 0; ks < 8; ks++) {
            const float x0  = __shfl_sync(0xffffffffu, c[ks][0], s0, 4);
            const float x1  = __shfl_sync(0xffffffffu, c[ks][1], s0, 4);
            const float y0  = __shfl_sync(0xffffffffu, c[ks][2], s0, 4);
            const float y1  = __shfl_sync(0xffffffffu, c[ks][3], s0, 4);
            const float x0b = __shfl_sync(0xffffffffu, c[ks][0], s0 + 2, 4);
            const float x1b = __shfl_sync(0xffffffffu, c[ks][1], s0 + 2, 4);
            const float y0b = __shfl_sync(0xffffffffu, c[ks][2], s0 + 2, 4);
            const float y1b = __shfl_sync(0xffffffffu, c[ks][3], s0 + 2, 4);
            uint32_t pa[4];
            pa[0] = __float_as_uint(sel ? x1  : x0);
            pa[1] = __float_as_uint(sel ? y1  : y0);
            pa[2] = __float_as_uint(sel ? x1b : x0b);
            pa[3] = __float_as_uint(sel ? y1b : y0b);

            uint32_t vf[8][2];
            const uint32_t vr0 = vB + (ks * 8 + tig) * 256;
            const uint32_t vr4 = vB + (ks * 8 + tig + 4) * 256;
#pragma unroll
            for (int nt = 0; nt < 8; nt++) {
                const uint32_t coff = ((nt * 8 + g) * 4) ^ vswz;
                vf[nt][0] = lds32(vr0 + coff);
                vf[nt][1] = lds32(vr4 + coff);
            }
#pragma unroll
            for (int nt = 0; nt < 8; nt++)
                mma_16n8k8(o[nt], pa, vf[nt]);
        }
        __syncthreads();
    }

    // epilogue: O /= l, convert to fp16 for the proj GEMM
    const float inv0 = 1.0f / l_r[0];
    const float inv1 = 1.0f / l_r[1];
    const size_t row0 = (size_t)b * SEQ + q0 + wid * 16 + g;
    const size_t row1 = row0 + 8;
#pragma unroll
    for (int nt = 0; nt < 8; nt++) {
        const int col = h * HDIM + nt * 8 + 2 * tig;
        __half2 v0 = __floats2half2_rn(o[nt][0] * inv0, o[nt][1] * inv0);
        __half2 v1 = __floats2half2_rn(o[nt][2] * inv1, o[nt][3] * inv1);
        *(__half2*)(out + row0 * DIM + col) = v0;
        *(__half2*)(out + row1 * DIM + col) = v1;
    }
}

// ===========================================================================
// Launch
// ===========================================================================
extern "C" void kernel_launch(void* const* d_in, const int* in_sizes, int n_in,
                              void* d_out, int out_size)
{
    const float* x    = (const float*)d_in[0];
    const float* Wqkv = (const float*)d_in[1];
    const float* bqkv = (const float*)d_in[2];
    const float* W1   = (const float*)d_in[3];
    const float* b1   = (const float*)d_in[4];
    float* out = (float*)d_out;

    float*  qkv_p;
    __half *attn_p, *xh_p, *wh_p, *w1h_p;
    cudaGetSymbolAddress((void**)&qkv_p,  g_qkv);
    cudaGetSymbolAddress((void**)&attn_p, g_attn_h);
    cudaGetSymbolAddress((void**)&xh_p,   g_xh);
    cudaGetSymbolAddress((void**)&wh_p,   g_wh);
    cudaGetSymbolAddress((void**)&w1h_p,  g_w1h);

    cudaFuncSetAttribute(gemm_mma_f16<true>,
                         cudaFuncAttributeMaxDynamicSharedMemorySize, HGEMM_SMEM);
    cudaFuncSetAttribute(gemm_mma_f16<false>,
                         cudaFuncAttributeMaxDynamicSharedMemorySize, HGEMM_SMEM);
    cudaFuncSetAttribute(flash_attn_tc,
                         cudaFuncAttributeMaxDynamicSharedMemorySize, FA_SMEM);

    // 0) convert GEMM operands to fp16
    to_half<<<(ROWS * DIM / 2 + 255) / 256, 256>>>(x, xh_p, ROWS * DIM / 2);
    to_half<<<(QKVDIM * DIM / 2 + 255) / 256, 256>>>(Wqkv, wh_p, QKVDIM * DIM / 2);
    to_half<<<(DIM * DIM / 2 + 255) / 256, 256>>>(W1, w1h_p, DIM * DIM / 2);

    // 1) QKV projection (fp16 HMMA; epilogue tf32-rounds for attention)
    {
        dim3 grid(QKVDIM / 256, ROWS / 128);
        gemm_mma_f16<true><<<grid, 256, HGEMM_SMEM>>>(xh_p, wh_p, bqkv, qkv_p,
                                                      ROWS, QKVDIM, DIM);
    }

    // 2) Tensor-core flash attention (tf32; epilogue emits fp16)
    {
        dim3 grid(SEQ / 64, HEADS, BATCH);
        flash_attn_tc<<<grid, 128, FA_SMEM>>>(qkv_p, attn_p);
    }

    // 3) Output projection (fp16 HMMA, fp32 out)
    {
        dim3 grid(DIM / 256, ROWS / 128);
        gemm_mma_f16<false><<<grid, 256, HGEMM_SMEM>>>(attn_p, w1h_p, b1, out,
                                                       ROWS, DIM, DIM);
    }
}

// round 10
// speedup vs baseline: 7.3971x; 1.3685x over previous
#include <cuda_runtime.h>
#include <cuda_bf16.h>
#include <cuda_fp16.h>
#include <cstdint>

// ---------------------------------------------------------------------------
// Fused transformer block, fp32 in/out. All math on fp16 HMMA m16n8k16
// (fp32 accumulate). fp16 mantissa == tf32 mantissa -> same rounding error.
//   qkv = x @ Wqkv^T + bqkv   (4096x3072x1024)  -> fp16 qkv
//   attention: 16 heads, d=64, scale 1/32       -> fp16 flash attention
//   out = attn @ W1^T + b1    (4096x1024x1024)  -> fp32 out
// ---------------------------------------------------------------------------

#define BATCH   4
#define SEQ     1024
#define DIM     1024
#define HEADS   16
#define HDIM    64
#define ROWS    (BATCH * SEQ)      // 4096
#define QKVDIM  (3 * DIM)          // 3072

__device__ __align__(256) __half g_qkv_h[ROWS * QKVDIM];
__device__ __align__(256) __half g_attn_h[ROWS * DIM];
__device__ __align__(256) __half g_xh[ROWS * DIM];
__device__ __align__(256) __half g_wh[QKVDIM * DIM];
__device__ __align__(256) __half g_w1h[DIM * DIM];

// ===========================================================================
// helpers
// ===========================================================================
__device__ __forceinline__ uint32_t smem_u32(const void* p) {
    uint32_t a;
    asm("{ .reg .u64 t; cvta.to.shared.u64 t, %1; cvt.u32.u64 %0, t; }"
        : "=r"(a) : "l"(p));
    return a;
}
__device__ __forceinline__ uint32_t lds32(uint32_t addr) {
    uint32_t v;
    asm volatile("ld.shared.b32 %0, [%1];" : "=r"(v) : "r"(addr));
    return v;
}
__device__ __forceinline__ void cp16(uint32_t dst, const void* src) {
    asm volatile("cp.async.cg.shared.global [%0], [%1], 16;" :: "r"(dst), "l"(src));
}
#define CP_COMMIT() asm volatile("cp.async.commit_group;" ::: "memory")
#define CP_WAIT(n)  asm volatile("cp.async.wait_group %0;" :: "n"(n) : "memory")

// fp16 m16n8k16, fp32 accumulate
__device__ __forceinline__ void mma_16n8k16_f16(
    float* c, const uint32_t* a, const uint32_t* b)
{
    asm volatile(
        "mma.sync.aligned.m16n8k16.row.col.f32.f16.f16.f32 "
        "{%0,%1,%2,%3}, {%4,%5,%6,%7}, {%8,%9}, {%0,%1,%2,%3};"
        : "+f"(c[0]), "+f"(c[1]), "+f"(c[2]), "+f"(c[3])
        : "r"(a[0]), "r"(a[1]), "r"(a[2]), "r"(a[3]), "r"(b[0]), "r"(b[1]));
}

__device__ __forceinline__ void ldmx4(
    uint32_t& r0, uint32_t& r1, uint32_t& r2, uint32_t& r3, uint32_t addr)
{
    asm volatile(
        "ldmatrix.sync.aligned.m8n8.x4.shared.b16 {%0,%1,%2,%3}, [%4];"
        : "=r"(r0), "=r"(r1), "=r"(r2), "=r"(r3) : "r"(addr));
}
__device__ __forceinline__ void ldmx4t(
    uint32_t& r0, uint32_t& r1, uint32_t& r2, uint32_t& r3, uint32_t addr)
{
    asm volatile(
        "ldmatrix.sync.aligned.m8n8.x4.trans.shared.b16 {%0,%1,%2,%3}, [%4];"
        : "=r"(r0), "=r"(r1), "=r"(r2), "=r"(r3) : "r"(addr));
}

// ===========================================================================
// fp32 -> fp16 conversion kernel
// ===========================================================================
__global__ __launch_bounds__(256) void to_half(
    const float* __restrict__ in, __half* __restrict__ out, int n2)
{
    int i = blockIdx.x * blockDim.x + threadIdx.x;
    if (i >= n2) return;
    float2 v = ((const float2*)in)[i];
    ((__half2*)out)[i] = __floats2half2_rn(v.x, v.y);
}

// ===========================================================================
// fp16 NT GEMM + bias:  C[M,N] = A[M,K] @ B[N,K]^T + bias[N]   (fp32 accum)
// CTA tile 128x256, K-tile 64, 2-stage cp.async, 256 thr,
// warp grid 2x4, warp tile 64x64, m16n8k16.
// HALF_OUT: write fp16 (for tensors feeding later MMAs), else fp32.
// ===========================================================================
#define HTK       64
#define HROWB     144
#define HATILE    (128 * HROWB)
#define HBTILE    (256 * HROWB)
#define HSTAGE    (HATILE + HBTILE)          // 55296
#define HGEMM_SMEM (2 * HSTAGE)              // 110592 B

template <bool HALF_OUT>
__global__ __launch_bounds__(256) void gemm_mma_f16(
    const __half* __restrict__ A, const __half* __restrict__ B,
    const float* __restrict__ bias, void* __restrict__ Cout,
    int M, int N, int K)
{
    extern __shared__ char smem[];
    const uint32_t sb = smem_u32(smem);
    const int tid    = threadIdx.x;
    const int wid    = tid >> 5;
    const int lane   = tid & 31;
    const int g      = lane >> 2;
    const int tig    = lane & 3;
    const int warp_m = wid & 1;
    const int warp_n = wid >> 1;
    const int m0     = blockIdx.y * 128;
    const int n0     = blockIdx.x * 256;

    float c[4][8][4];
#pragma unroll
    for (int mt = 0; mt < 4; mt++)
#pragma unroll
        for (int nt = 0; nt < 8; nt++)
#pragma unroll
            for (int r = 0; r < 4; r++) c[mt][nt][r] = 0.0f;

    auto load_tile = [&](int slot, int k0) {
        const uint32_t aB = sb + slot * HSTAGE;
        const uint32_t bB = aB + HATILE;
#pragma unroll
        for (int i = 0; i < 4; i++) {
            const int idx = i * 256 + tid;
            const int row = idx >> 3;
            const int seg = idx & 7;
            cp16(aB + row * HROWB + seg * 16, A + (size_t)(m0 + row) * K + k0 + seg * 8);
        }
#pragma unroll
        for (int i = 0; i < 8; i++) {
            const int idx = i * 256 + tid;
            const int row = idx >> 3;
            const int seg = idx & 7;
            cp16(bB + row * HROWB + seg * 16, B + (size_t)(n0 + row) * K + k0 + seg * 8);
        }
        CP_COMMIT();
    };

    const int NT = K / HTK;
    load_tile(0, 0);

    for (int t = 0; t < NT; t++) {
        if (t + 1 < NT) {
            load_tile((t + 1) & 1, (t + 1) * HTK);
            CP_WAIT(1);
        } else {
            CP_WAIT(0);
        }
        __syncthreads();

        const uint32_t aB = sb + (t & 1) * HSTAGE;
        const uint32_t bB = aB + HATILE;

#pragma unroll
        for (int kk = 0; kk < HTK; kk += 16) {
            uint32_t af[4][4];
            uint32_t bf[8][2];
#pragma unroll
            for (int mt = 0; mt < 4; mt++) {
                const int row = warp_m * 64 + mt * 16;
                const uint32_t base = aB + (row + g) * HROWB + (kk + 2 * tig) * 2;
                af[mt][0] = lds32(base);
                af[mt][1] = lds32(base + 8 * HROWB);
                af[mt][2] = lds32(base + 16);
                af[mt][3] = lds32(base + 8 * HROWB + 16);
            }
#pragma unroll
            for (int nt = 0; nt < 8; nt++) {
                const int col = warp_n * 64 + nt * 8 + g;
                const uint32_t base = bB + col * HROWB + (kk + 2 * tig) * 2;
                bf[nt][0] = lds32(base);
                bf[nt][1] = lds32(base + 16);
            }
#pragma unroll
            for (int mt = 0; mt < 4; mt++)
#pragma unroll
                for (int nt = 0; nt < 8; nt++)
                    mma_16n8k16_f16(c[mt][nt], af[mt], bf[nt]);
        }
        __syncthreads();
    }

#pragma unroll
    for (int mt = 0; mt < 4; mt++) {
        const int row = m0 + warp_m * 64 + mt * 16 + g;
#pragma unroll
        for (int nt = 0; nt < 8; nt++) {
            const int col = n0 + warp_n * 64 + nt * 8 + tig * 2;
            const float bx = bias[col];
            const float by = bias[col + 1];
            if (HALF_OUT) {
                __half* C = (__half*)Cout;
                *(__half2*)(C + (size_t)row * N + col) =
                    __floats2half2_rn(c[mt][nt][0] + bx, c[mt][nt][1] + by);
                *(__half2*)(C + (size_t)(row + 8) * N + col) =
                    __floats2half2_rn(c[mt][nt][2] + bx, c[mt][nt][3] + by);
            } else {
                float* C = (float*)Cout;
                *(float2*)(C + (size_t)row * N + col) =
                    make_float2(c[mt][nt][0] + bx, c[mt][nt][1] + by);
                *(float2*)(C + (size_t)(row + 8) * N + col) =
                    make_float2(c[mt][nt][2] + bx, c[mt][nt][3] + by);
            }
        }
    }
}

// ===========================================================================
// fp16 flash attention. 128 thr (4 warps), 64 q-rows, 64-key tiles,
// double-buffered cp.async K/V. All tiles [64 rows][64 halfs] @ stride 144 B
// (ldmatrix rows hit rotating 16B offsets -> conflict-free).
// QK^T and PV via m16n8k16; P: C-frag == A-frag layout -> pack only.
// ===========================================================================
#define FAS       144                       // smem row stride (bytes)
#define FA_Q      0
#define FA_TILE   (64 * FAS)                // 9216
#define FA_K      FA_TILE
#define FA_V      (FA_K + 2 * FA_TILE)
#define FA_SMEM   (FA_V + 2 * FA_TILE)      // 46080 B

__global__ __launch_bounds__(128) void flash_attn_f16(
    const __half* __restrict__ qkv, __half* __restrict__ out)
{
    extern __shared__ char smem[];
    const uint32_t sb = smem_u32(smem);
    const int tid  = threadIdx.x;
    const int wid  = tid >> 5;
    const int lane = tid & 31;
    const int g    = lane >> 2;
    const int tig  = lane & 3;
    const int q0   = blockIdx.x * 64;
    const int h    = blockIdx.y;
    const int b    = blockIdx.z;

    const __half* qb = qkv + (size_t)b * SEQ * QKVDIM + (size_t)h * HDIM;
    const __half* kb = qb + DIM;
    const __half* vb = qb + 2 * DIM;

    // Q tile: 64 rows x 64 halfs (128 B) -> 8 segs/row, 512 cp16 / 128 thr
#pragma unroll
    for (int i = 0; i < 4; i++) {
        const int idx = i * 128 + tid;
        const int row = idx >> 3;
        const int seg = idx & 7;
        cp16(sb + FA_Q + row * FAS + seg * 16,
             qb + (size_t)(q0 + row) * QKVDIM + seg * 8);
    }
    CP_COMMIT();

    auto load_kv = [&](int slot, int jt) {
        const int j0 = jt * 64;
        const uint32_t kB = sb + FA_K + slot * FA_TILE;
        const uint32_t vB = sb + FA_V + slot * FA_TILE;
#pragma unroll
        for (int i = 0; i < 4; i++) {
            const int idx = i * 128 + tid;
            const int row = idx >> 3;
            const int seg = idx & 7;
            cp16(kB + row * FAS + seg * 16, kb + (size_t)(j0 + row) * QKVDIM + seg * 8);
            cp16(vB + row * FAS + seg * 16, vb + (size_t)(j0 + row) * QKVDIM + seg * 8);
        }
        CP_COMMIT();
    };

    load_kv(0, 0);
    CP_WAIT(1);            // Q group done
    __syncthreads();

    // ldmatrix lane decomposition
    const int lr  = lane & 7;          // row within 8x8 tile
    const int grp = lane >> 3;         // which fragment this lane feeds

    // --- Q fragments (A-frag), pre-scaled by 1/32 (exact in fp16) ---
    uint32_t qf[4][4];
    {
        const uint32_t qbase = sb + FA_Q + (wid * 16) * FAS;
        const int s1 = grp & 1;        // +8 rows for frags 1,3
        const int s2 = grp >> 1;       // +8 k for frags 2,3
        const __half2 sc = __float2half2_rn(0.03125f);
#pragma unroll
        for (int ks = 0; ks < 4; ks++) {
            const uint32_t addr = qbase + (lr + 8 * s1) * FAS + (ks * 16 + 8 * s2) * 2;
            ldmx4(qf[ks][0], qf[ks][1], qf[ks][2], qf[ks][3], addr);
#pragma unroll
            for (int j = 0; j < 4; j++) {
                __half2 v = *(__half2*)&qf[ks][j];
                v = __hmul2(v, sc);
                qf[ks][j] = *(uint32_t*)&v;
            }
        }
    }

    float o[8][4];
#pragma unroll
    for (int nt = 0; nt < 8; nt++)
#pragma unroll
        for (int r = 0; r < 4; r++) o[nt][r] = 0.0f;
    float m_r[2] = {-1e30f, -1e30f};
    float l_r[2] = {0.0f, 0.0f};

    // K/V ldmatrix address components: fragment j covers
    //   nt = 2*i + (grp>>1), k-half = grp&1, row-in-tile = lr
    const int knt = grp >> 1;          // 0 or 1 (n-tile offset within x4)
    const int kkh = grp & 1;           // k-half

    for (int jt = 0; jt < SEQ / 64; jt++) {
        if (jt + 1 < SEQ / 64) {
            load_kv((jt + 1) & 1, jt + 1);
            CP_WAIT(1);
        } else {
            CP_WAIT(0);
        }
        __syncthreads();

        const uint32_t kB = sb + FA_K + (jt & 1) * FA_TILE;
        const uint32_t vB = sb + FA_V + (jt & 1) * FA_TILE;

        // --- S = (Q/32) @ K^T : m16n8k16, 4 k-steps x 8 n-tiles ---
        float c[8][4];
#pragma unroll
        for (int nt = 0; nt < 8; nt++)
#pragma unroll
            for (int r = 0; r < 4; r++) c[nt][r] = 0.0f;

#pragma unroll
        for (int ks = 0; ks < 4; ks++) {
            uint32_t kf[8][2];
#pragma unroll
            for (int i = 0; i < 4; i++) {
                // keys rows: (2i+knt)*8 + lr ; k cols: ks*16 + kkh*8
                const uint32_t addr =
                    kB + ((2 * i + knt) * 8 + lr) * FAS + (ks * 16 + kkh * 8) * 2;
                ldmx4(kf[2 * i][0], kf[2 * i][1], kf[2 * i + 1][0], kf[2 * i + 1][1], addr);
            }
#pragma unroll
            for (int nt = 0; nt < 8; nt++)
                mma_16n8k16_f16(c[nt], qf[ks], kf[nt]);
        }

        // --- online softmax (rows g and g+8 of this warp's 16) ---
#pragma unroll
        for (int r = 0; r < 2; r++) {
            float mx = -1e30f;
#pragma unroll
            for (int nt = 0; nt < 8; nt++) {
                mx = fmaxf(mx, c[nt][2 * r]);
                mx = fmaxf(mx, c[nt][2 * r + 1]);
            }
            mx = fmaxf(mx, __shfl_xor_sync(0xffffffffu, mx, 1));
            mx = fmaxf(mx, __shfl_xor_sync(0xffffffffu, mx, 2));
            const float mnew  = fmaxf(m_r[r], mx);
            const float alpha = __expf(m_r[r] - mnew);
            float sum = 0.0f;
#pragma unroll
            for (int nt = 0; nt < 8; nt++) {
                const float p0 = __expf(c[nt][2 * r]     - mnew);
                const float p1 = __expf(c[nt][2 * r + 1] - mnew);
                c[nt][2 * r] = p0; c[nt][2 * r + 1] = p1;
                sum += p0 + p1;
            }
            sum += __shfl_xor_sync(0xffffffffu, sum, 1);
            sum += __shfl_xor_sync(0xffffffffu, sum, 2);
            l_r[r] = l_r[r] * alpha + sum;
            m_r[r] = mnew;
#pragma unroll
            for (int nt = 0; nt < 8; nt++) {
                o[nt][2 * r]     *= alpha;
                o[nt][2 * r + 1] *= alpha;
            }
        }

        // --- O += P @ V : pack P (C-frag == A-frag layout), ldmatrix.trans V
#pragma unroll
        for (int ks = 0; ks < 4; ks++) {
            uint32_t pa[4];
            {
                __half2 p0 = __floats2half2_rn(c[2 * ks][0],     c[2 * ks][1]);
                __half2 p1 = __floats2half2_rn(c[2 * ks][2],     c[2 * ks][3]);
                __half2 p2 = __floats2half2_rn(c[2 * ks + 1][0], c[2 * ks + 1][1]);
                __half2 p3 = __floats2half2_rn(c[2 * ks + 1][2], c[2 * ks + 1][3]);
                pa[0] = *(uint32_t*)&p0;
                pa[1] = *(uint32_t*)&p1;
                pa[2] = *(uint32_t*)&p2;
                pa[3] = *(uint32_t*)&p3;
            }
            uint32_t vf[8][2];
#pragma unroll
            for (int i = 0; i < 4; i++) {
                // keys rows: ks*16 + kkh*8 + lr ; d cols: (2i+knt)*8
                const uint32_t addr =
                    vB + (ks * 16 + kkh * 8 + lr) * FAS + ((2 * i + knt) * 8) * 2;
                ldmx4t(vf[2 * i][0], vf[2 * i][1], vf[2 * i + 1][0], vf[2 * i + 1][1], addr);
            }
#pragma unroll
            for (int nt = 0; nt < 8; nt++)
                mma_16n8k16_f16(o[nt], pa, vf[nt]);
        }
        __syncthreads();
    }

    // --- epilogue: O /= l, write fp16 (feeds proj GEMM) ---
    const float inv0 = 1.0f / l_r[0];
    const float inv1 = 1.0f / l_r[1];
    const size_t row0 = (size_t)b * SEQ + q0 + wid * 16 + g;
    const size_t row1 = row0 + 8;
#pragma unroll
    for (int nt = 0; nt < 8; nt++) {
        const int col = h * HDIM + nt * 8 + 2 * tig;
        *(__half2*)(out + row0 * DIM + col) =
            __floats2half2_rn(o[nt][0] * inv0, o[nt][1] * inv0);
        *(__half2*)(out + row1 * DIM + col) =
            __floats2half2_rn(o[nt][2] * inv1, o[nt][3] * inv1);
    }
}

// ===========================================================================
// Launch
// ===========================================================================
extern "C" void kernel_launch(void* const* d_in, const int* in_sizes, int n_in,
                              void* d_out, int out_size)
{
    const float* x    = (const float*)d_in[0];
    const float* Wqkv = (const float*)d_in[1];
    const float* bqkv = (const float*)d_in[2];
    const float* W1   = (const float*)d_in[3];
    const float* b1   = (const float*)d_in[4];
    float* out = (float*)d_out;

    __half *qkv_p, *attn_p, *xh_p, *wh_p, *w1h_p;
    cudaGetSymbolAddress((void**)&qkv_p,  g_qkv_h);
    cudaGetSymbolAddress((void**)&attn_p, g_attn_h);
    cudaGetSymbolAddress((void**)&xh_p,   g_xh);
    cudaGetSymbolAddress((void**)&wh_p,   g_wh);
    cudaGetSymbolAddress((void**)&w1h_p,  g_w1h);

    cudaFuncSetAttribute(gemm_mma_f16<true>,
                         cudaFuncAttributeMaxDynamicSharedMemorySize, HGEMM_SMEM);
    cudaFuncSetAttribute(gemm_mma_f16<false>,
                         cudaFuncAttributeMaxDynamicSharedMemorySize, HGEMM_SMEM);
    cudaFuncSetAttribute(flash_attn_f16,
                         cudaFuncAttributeMaxDynamicSharedMemorySize, FA_SMEM);

    // 0) convert GEMM operands to fp16
    to_half<<<(ROWS * DIM / 2 + 255) / 256, 256>>>(x, xh_p, ROWS * DIM / 2);
    to_half<<<(QKVDIM * DIM / 2 + 255) / 256, 256>>>(Wqkv, wh_p, QKVDIM * DIM / 2);
    to_half<<<(DIM * DIM / 2 + 255) / 256, 256>>>(W1, w1h_p, DIM * DIM / 2);

    // 1) QKV projection -> fp16 qkv
    {
        dim3 grid(QKVDIM / 256, ROWS / 128);
        gemm_mma_f16<true><<<grid, 256, HGEMM_SMEM>>>(xh_p, wh_p, bqkv, qkv_p,
                                                      ROWS, QKVDIM, DIM);
    }

    // 2) fp16 flash attention -> fp16 attn
    {
        dim3 grid(SEQ / 64, HEADS, BATCH);
        flash_attn_f16<<<grid, 128, FA_SMEM>>>(qkv_p, attn_p);
    }

    // 3) Output projection -> fp32 out
    {
        dim3 grid(DIM / 256, ROWS / 128);
        gemm_mma_f16<false><<<grid, 256, HGEMM_SMEM>>>(attn_p, w1h_p, b1, out,
                                                       ROWS, DIM, DIM);
    }
}

// round 11
// speedup vs baseline: 7.5855x; 1.0255x over previous
#include <cuda_runtime.h>
#include <cuda_bf16.h>
#include <cuda_fp16.h>
#include <cstdint>

// ---------------------------------------------------------------------------
// Fused transformer block, fp32 in/out. All math on fp16 HMMA m16n8k16
// (fp32 accumulate). fp16 mantissa == tf32 mantissa -> same rounding error.
//   qkv = x @ Wqkv^T + bqkv   (4096x3072x1024)  -> fp16 qkv
//   attention: 16 heads, d=64, scale 1/32       -> fp16 flash attention
//   out = attn @ W1^T + b1    (4096x1024x1024)  -> fp32 out
// R11: GEMM fragment loads via ldmatrix.x4 + double-buffered fragments.
// ---------------------------------------------------------------------------

#define BATCH   4
#define SEQ     1024
#define DIM     1024
#define HEADS   16
#define HDIM    64
#define ROWS    (BATCH * SEQ)      // 4096
#define QKVDIM  (3 * DIM)          // 3072

__device__ __align__(256) __half g_qkv_h[ROWS * QKVDIM];
__device__ __align__(256) __half g_attn_h[ROWS * DIM];
__device__ __align__(256) __half g_xh[ROWS * DIM];
__device__ __align__(256) __half g_wh[QKVDIM * DIM];
__device__ __align__(256) __half g_w1h[DIM * DIM];

// ===========================================================================
// helpers
// ===========================================================================
__device__ __forceinline__ uint32_t smem_u32(const void* p) {
    uint32_t a;
    asm("{ .reg .u64 t; cvta.to.shared.u64 t, %1; cvt.u32.u64 %0, t; }"
        : "=r"(a) : "l"(p));
    return a;
}
__device__ __forceinline__ void cp16(uint32_t dst, const void* src) {
    asm volatile("cp.async.cg.shared.global [%0], [%1], 16;" :: "r"(dst), "l"(src));
}
#define CP_COMMIT() asm volatile("cp.async.commit_group;" ::: "memory")
#define CP_WAIT(n)  asm volatile("cp.async.wait_group %0;" :: "n"(n) : "memory")

// fp16 m16n8k16, fp32 accumulate
__device__ __forceinline__ void mma_16n8k16_f16(
    float* c, const uint32_t* a, const uint32_t* b)
{
    asm volatile(
        "mma.sync.aligned.m16n8k16.row.col.f32.f16.f16.f32 "
        "{%0,%1,%2,%3}, {%4,%5,%6,%7}, {%8,%9}, {%0,%1,%2,%3};"
        : "+f"(c[0]), "+f"(c[1]), "+f"(c[2]), "+f"(c[3])
        : "r"(a[0]), "r"(a[1]), "r"(a[2]), "r"(a[3]), "r"(b[0]), "r"(b[1]));
}

__device__ __forceinline__ void ldmx4(
    uint32_t& r0, uint32_t& r1, uint32_t& r2, uint32_t& r3, uint32_t addr)
{
    asm volatile(
        "ldmatrix.sync.aligned.m8n8.x4.shared.b16 {%0,%1,%2,%3}, [%4];"
        : "=r"(r0), "=r"(r1), "=r"(r2), "=r"(r3) : "r"(addr));
}
__device__ __forceinline__ void ldmx4t(
    uint32_t& r0, uint32_t& r1, uint32_t& r2, uint32_t& r3, uint32_t addr)
{
    asm volatile(
        "ldmatrix.sync.aligned.m8n8.x4.trans.shared.b16 {%0,%1,%2,%3}, [%4];"
        : "=r"(r0), "=r"(r1), "=r"(r2), "=r"(r3) : "r"(addr));
}

// ===========================================================================
// fp32 -> fp16 conversion kernel
// ===========================================================================
__global__ __launch_bounds__(256) void to_half(
    const float* __restrict__ in, __half* __restrict__ out, int n2)
{
    int i = blockIdx.x * blockDim.x + threadIdx.x;
    if (i >= n2) return;
    float2 v = ((const float2*)in)[i];
    ((__half2*)out)[i] = __floats2half2_rn(v.x, v.y);
}

// ===========================================================================
// fp16 NT GEMM + bias:  C[M,N] = A[M,K] @ B[N,K]^T + bias[N]   (fp32 accum)
// CTA tile 128x256, K-tile 64, 2-stage cp.async, 256 thr,
// warp grid 2x4, warp tile 64x64, m16n8k16.
// Fragments via ldmatrix.x4 (8 ops/k-step vs 32 LDS), double-buffered so
// the 29-cyc LDS latency hides behind the previous k-step's HMMAs.
// ===========================================================================
#define HTK       64
#define HROWB     144
#define HATILE    (128 * HROWB)
#define HBTILE    (256 * HROWB)
#define HSTAGE    (HATILE + HBTILE)          // 55296
#define HGEMM_SMEM (2 * HSTAGE)              // 110592 B

template <bool HALF_OUT>
__global__ __launch_bounds__(256) void gemm_mma_f16(
    const __half* __restrict__ A, const __half* __restrict__ B,
    const float* __restrict__ bias, void* __restrict__ Cout,
    int M, int N, int K)
{
    extern __shared__ char smem[];
    const uint32_t sb = smem_u32(smem);
    const int tid    = threadIdx.x;
    const int wid    = tid >> 5;
    const int lane   = tid & 31;
    const int g      = lane >> 2;
    const int tig    = lane & 3;
    const int warp_m = wid & 1;
    const int warp_n = wid >> 1;
    const int m0     = blockIdx.y * 128;
    const int n0     = blockIdx.x * 256;

    // ldmatrix lane decomposition
    const int lr  = lane & 7;
    const int grp = lane >> 3;
    const int s1  = grp & 1;           // A: +8 rows
    const int s2  = grp >> 1;          // A: +8 k
    const int knt = grp >> 1;          // B: odd/even n-tile
    const int kkh = grp & 1;           // B: k-half

    float c[4][8][4];
#pragma unroll
    for (int mt = 0; mt < 4; mt++)
#pragma unroll
        for (int nt = 0; nt < 8; nt++)
#pragma unroll
            for (int r = 0; r < 4; r++) c[mt][nt][r] = 0.0f;

    auto load_tile = [&](int slot, int k0) {
        const uint32_t aB = sb + slot * HSTAGE;
        const uint32_t bB = aB + HATILE;
#pragma unroll
        for (int i = 0; i < 4; i++) {
            const int idx = i * 256 + tid;
            const int row = idx >> 3;
            const int seg = idx & 7;
            cp16(aB + row * HROWB + seg * 16, A + (size_t)(m0 + row) * K + k0 + seg * 8);
        }
#pragma unroll
        for (int i = 0; i < 8; i++) {
            const int idx = i * 256 + tid;
            const int row = idx >> 3;
            const int seg = idx & 7;
            cp16(bB + row * HROWB + seg * 16, B + (size_t)(n0 + row) * K + k0 + seg * 8);
        }
        CP_COMMIT();
    };

    // fragment loader for one 16-wide k-step (kk in halfs) from tile base
    auto load_frags = [&](uint32_t aB, uint32_t bB, int kk,
                          uint32_t af[4][4], uint32_t bf[8][2]) {
        const uint32_t arow = aB + (warp_m * 64 + lr + 8 * s1) * HROWB
                                 + (kk + 8 * s2) * 2;
#pragma unroll
        for (int mt = 0; mt < 4; mt++)
            ldmx4(af[mt][0], af[mt][1], af[mt][2], af[mt][3],
                  arow + mt * 16 * HROWB);
        const uint32_t brow = bB + (warp_n * 64 + knt * 8 + lr) * HROWB
                                 + (kk + kkh * 8) * 2;
#pragma unroll
        for (int i = 0; i < 4; i++)
            ldmx4(bf[2 * i][0], bf[2 * i][1], bf[2 * i + 1][0], bf[2 * i + 1][1],
                  brow + i * 16 * HROWB);
    };

    const int NT = K / HTK;
    load_tile(0, 0);

    uint32_t af[2][4][4];
    uint32_t bf[2][8][2];

    for (int t = 0; t < NT; t++) {
        if (t + 1 < NT) {
            load_tile((t + 1) & 1, (t + 1) * HTK);
            CP_WAIT(1);
        } else {
            CP_WAIT(0);
        }
        __syncthreads();

        const uint32_t aB = sb + (t & 1) * HSTAGE;
        const uint32_t bB = aB + HATILE;

        load_frags(aB, bB, 0, af[0], bf[0]);
#pragma unroll
        for (int ks = 0; ks < 4; ks++) {
            const int cur = ks & 1;
            if (ks < 3)
                load_frags(aB, bB, (ks + 1) * 16, af[cur ^ 1], bf[cur ^ 1]);
#pragma unroll
            for (int mt = 0; mt < 4; mt++)
#pragma unroll
                for (int nt = 0; nt < 8; nt++)
                    mma_16n8k16_f16(c[mt][nt], af[cur][mt], bf[cur][nt]);
        }
        __syncthreads();
    }

#pragma unroll
    for (int mt = 0; mt < 4; mt++) {
        const int row = m0 + warp_m * 64 + mt * 16 + g;
#pragma unroll
        for (int nt = 0; nt < 8; nt++) {
            const int col = n0 + warp_n * 64 + nt * 8 + tig * 2;
            const float bx = bias[col];
            const float by = bias[col + 1];
            if (HALF_OUT) {
                __half* C = (__half*)Cout;
                *(__half2*)(C + (size_t)row * N + col) =
                    __floats2half2_rn(c[mt][nt][0] + bx, c[mt][nt][1] + by);
                *(__half2*)(C + (size_t)(row + 8) * N + col) =
                    __floats2half2_rn(c[mt][nt][2] + bx, c[mt][nt][3] + by);
            } else {
                float* C = (float*)Cout;
                *(float2*)(C + (size_t)row * N + col) =
                    make_float2(c[mt][nt][0] + bx, c[mt][nt][1] + by);
                *(float2*)(C + (size_t)(row + 8) * N + col) =
                    make_float2(c[mt][nt][2] + bx, c[mt][nt][3] + by);
            }
        }
    }
}

// ===========================================================================
// fp16 flash attention (unchanged from R10, passing).
// ===========================================================================
#define FAS       144
#define FA_Q      0
#define FA_TILE   (64 * FAS)
#define FA_K      FA_TILE
#define FA_V      (FA_K + 2 * FA_TILE)
#define FA_SMEM   (FA_V + 2 * FA_TILE)      // 46080 B

__global__ __launch_bounds__(128) void flash_attn_f16(
    const __half* __restrict__ qkv, __half* __restrict__ out)
{
    extern __shared__ char smem[];
    const uint32_t sb = smem_u32(smem);
    const int tid  = threadIdx.x;
    const int wid  = tid >> 5;
    const int lane = tid & 31;
    const int g    = lane >> 2;
    const int tig  = lane & 3;
    const int q0   = blockIdx.x * 64;
    const int h    = blockIdx.y;
    const int b    = blockIdx.z;

    const __half* qb = qkv + (size_t)b * SEQ * QKVDIM + (size_t)h * HDIM;
    const __half* kb = qb + DIM;
    const __half* vb = qb + 2 * DIM;

#pragma unroll
    for (int i = 0; i < 4; i++) {
        const int idx = i * 128 + tid;
        const int row = idx >> 3;
        const int seg = idx & 7;
        cp16(sb + FA_Q + row * FAS + seg * 16,
             qb + (size_t)(q0 + row) * QKVDIM + seg * 8);
    }
    CP_COMMIT();

    auto load_kv = [&](int slot, int jt) {
        const int j0 = jt * 64;
        const uint32_t kB = sb + FA_K + slot * FA_TILE;
        const uint32_t vB = sb + FA_V + slot * FA_TILE;
#pragma unroll
        for (int i = 0; i < 4; i++) {
            const int idx = i * 128 + tid;
            const int row = idx >> 3;
            const int seg = idx & 7;
            cp16(kB + row * FAS + seg * 16, kb + (size_t)(j0 + row) * QKVDIM + seg * 8);
            cp16(vB + row * FAS + seg * 16, vb + (size_t)(j0 + row) * QKVDIM + seg * 8);
        }
        CP_COMMIT();
    };

    load_kv(0, 0);
    CP_WAIT(1);
    __syncthreads();

    const int lr  = lane & 7;
    const int grp = lane >> 3;

    uint32_t qf[4][4];
    {
        const uint32_t qbase = sb + FA_Q + (wid * 16) * FAS;
        const int s1 = grp & 1;
        const int s2 = grp >> 1;
        const __half2 sc = __float2half2_rn(0.03125f);
#pragma unroll
        for (int ks = 0; ks < 4; ks++) {
            const uint32_t addr = qbase + (lr + 8 * s1) * FAS + (ks * 16 + 8 * s2) * 2;
            ldmx4(qf[ks][0], qf[ks][1], qf[ks][2], qf[ks][3], addr);
#pragma unroll
            for (int j = 0; j < 4; j++) {
                __half2 v = *(__half2*)&qf[ks][j];
                v = __hmul2(v, sc);
                qf[ks][j] = *(uint32_t*)&v;
            }
        }
    }

    float o[8][4];
#pragma unroll
    for (int nt = 0; nt < 8; nt++)
#pragma unroll
        for (int r = 0; r < 4; r++) o[nt][r] = 0.0f;
    float m_r[2] = {-1e30f, -1e30f};
    float l_r[2] = {0.0f, 0.0f};

    const int knt = grp >> 1;
    const int kkh = grp & 1;

    for (int jt = 0; jt < SEQ / 64; jt++) {
        if (jt + 1 < SEQ / 64) {
            load_kv((jt + 1) & 1, jt + 1);
            CP_WAIT(1);
        } else {
            CP_WAIT(0);
        }
        __syncthreads();

        const uint32_t kB = sb + FA_K + (jt & 1) * FA_TILE;
        const uint32_t vB = sb + FA_V + (jt & 1) * FA_TILE;

        float c[8][4];
#pragma unroll
        for (int nt = 0; nt < 8; nt++)
#pragma unroll
            for (int r = 0; r < 4; r++) c[nt][r] = 0.0f;

#pragma unroll
        for (int ks = 0; ks < 4; ks++) {
            uint32_t kf[8][2];
#pragma unroll
            for (int i = 0; i < 4; i++) {
                const uint32_t addr =
                    kB + ((2 * i + knt) * 8 + lr) * FAS + (ks * 16 + kkh * 8) * 2;
                ldmx4(kf[2 * i][0], kf[2 * i][1], kf[2 * i + 1][0], kf[2 * i + 1][1], addr);
            }
#pragma unroll
            for (int nt = 0; nt < 8; nt++)
                mma_16n8k16_f16(c[nt], qf[ks], kf[nt]);
        }

#pragma unroll
        for (int r = 0; r < 2; r++) {
            float mx = -1e30f;
#pragma unroll
            for (int nt = 0; nt < 8; nt++) {
                mx = fmaxf(mx, c[nt][2 * r]);
                mx = fmaxf(mx, c[nt][2 * r + 1]);
            }
            mx = fmaxf(mx, __shfl_xor_sync(0xffffffffu, mx, 1));
            mx = fmaxf(mx, __shfl_xor_sync(0xffffffffu, mx, 2));
            const float mnew  = fmaxf(m_r[r], mx);
            const float alpha = __expf(m_r[r] - mnew);
            float sum = 0.0f;
#pragma unroll
            for (int nt = 0; nt < 8; nt++) {
                const float p0 = __expf(c[nt][2 * r]     - mnew);
                const float p1 = __expf(c[nt][2 * r + 1] - mnew);
                c[nt][2 * r] = p0; c[nt][2 * r + 1] = p1;
                sum += p0 + p1;
            }
            sum += __shfl_xor_sync(0xffffffffu, sum, 1);
            sum += __shfl_xor_sync(0xffffffffu, sum, 2);
            l_r[r] = l_r[r] * alpha + sum;
            m_r[r] = mnew;
#pragma unroll
            for (int nt = 0; nt < 8; nt++) {
                o[nt][2 * r]     *= alpha;
                o[nt][2 * r + 1] *= alpha;
            }
        }

#pragma unroll
        for (int ks = 0; ks < 4; ks++) {
            uint32_t pa[4];
            {
                __half2 p0 = __floats2half2_rn(c[2 * ks][0],     c[2 * ks][1]);
                __half2 p1 = __floats2half2_rn(c[2 * ks][2],     c[2 * ks][3]);
                __half2 p2 = __floats2half2_rn(c[2 * ks + 1][0], c[2 * ks + 1][1]);
                __half2 p3 = __floats2half2_rn(c[2 * ks + 1][2], c[2 * ks + 1][3]);
                pa[0] = *(uint32_t*)&p0;
                pa[1] = *(uint32_t*)&p1;
                pa[2] = *(uint32_t*)&p2;
                pa[3] = *(uint32_t*)&p3;
            }
            uint32_t vf[8][2];
#pragma unroll
            for (int i = 0; i < 4; i++) {
                const uint32_t addr =
                    vB + (ks * 16 + kkh * 8 + lr) * FAS + ((2 * i + knt) * 8) * 2;
                ldmx4t(vf[2 * i][0], vf[2 * i][1], vf[2 * i + 1][0], vf[2 * i + 1][1], addr);
            }
#pragma unroll
            for (int nt = 0; nt < 8; nt++)
                mma_16n8k16_f16(o[nt], pa, vf[nt]);
        }
        __syncthreads();
    }

    const float inv0 = 1.0f / l_r[0];
    const float inv1 = 1.0f / l_r[1];
    const size_t row0 = (size_t)b * SEQ + q0 + wid * 16 + g;
    const size_t row1 = row0 + 8;
#pragma unroll
    for (int nt = 0; nt < 8; nt++) {
        const int col = h * HDIM + nt * 8 + 2 * tig;
        *(__half2*)(out + row0 * DIM + col) =
            __floats2half2_rn(o[nt][0] * inv0, o[nt][1] * inv0);
        *(__half2*)(out + row1 * DIM + col) =
            __floats2half2_rn(o[nt][2] * inv1, o[nt][3] * inv1);
    }
}

// ===========================================================================
// Launch
// ===========================================================================
extern "C" void kernel_launch(void* const* d_in, const int* in_sizes, int n_in,
                              void* d_out, int out_size)
{
    const float* x    = (const float*)d_in[0];
    const float* Wqkv = (const float*)d_in[1];
    const float* bqkv = (const float*)d_in[2];
    const float* W1   = (const float*)d_in[3];
    const float* b1   = (const float*)d_in[4];
    float* out = (float*)d_out;

    __half *qkv_p, *attn_p, *xh_p, *wh_p, *w1h_p;
    cudaGetSymbolAddress((void**)&qkv_p,  g_qkv_h);
    cudaGetSymbolAddress((void**)&attn_p, g_attn_h);
    cudaGetSymbolAddress((void**)&xh_p,   g_xh);
    cudaGetSymbolAddress((void**)&wh_p,   g_wh);
    cudaGetSymbolAddress((void**)&w1h_p,  g_w1h);

    cudaFuncSetAttribute(gemm_mma_f16<true>,
                         cudaFuncAttributeMaxDynamicSharedMemorySize, HGEMM_SMEM);
    cudaFuncSetAttribute(gemm_mma_f16<false>,
                         cudaFuncAttributeMaxDynamicSharedMemorySize, HGEMM_SMEM);
    cudaFuncSetAttribute(flash_attn_f16,
                         cudaFuncAttributeMaxDynamicSharedMemorySize, FA_SMEM);

    // 0) convert GEMM operands to fp16
    to_half<<<(ROWS * DIM / 2 + 255) / 256, 256>>>(x, xh_p, ROWS * DIM / 2);
    to_half<<<(QKVDIM * DIM / 2 + 255) / 256, 256>>>(Wqkv, wh_p, QKVDIM * DIM / 2);
    to_half<<<(DIM * DIM / 2 + 255) / 256, 256>>>(W1, w1h_p, DIM * DIM / 2);

    // 1) QKV projection -> fp16 qkv
    {
        dim3 grid(QKVDIM / 256, ROWS / 128);
        gemm_mma_f16<true><<<grid, 256, HGEMM_SMEM>>>(xh_p, wh_p, bqkv, qkv_p,
                                                      ROWS, QKVDIM, DIM);
    }

    // 2) fp16 flash attention -> fp16 attn
    {
        dim3 grid(SEQ / 64, HEADS, BATCH);
        flash_attn_f16<<<grid, 128, FA_SMEM>>>(qkv_p, attn_p);
    }

    // 3) Output projection -> fp32 out
    {
        dim3 grid(DIM / 256, ROWS / 128);
        gemm_mma_f16<false><<<grid, 256, HGEMM_SMEM>>>(attn_p, w1h_p, b1, out,
                                                       ROWS, DIM, DIM);
    }
}